// round 4
// baseline (speedup 1.0000x reference)
#include <cuda_runtime.h>
#include <math.h>

#define BS     4
#define NPTS   8192
#define KNB    32
#define CIN    64
#define CX     32
#define CF     96
#define COUT   64
#define KCONV  3072
#define PTOT   32768
#define CHUNK  8192
#define NCHUNK (PTOT / CHUNK)

// ---- device scratch (allocation-free: static __device__ globals) ----
__device__ float g_ft[BS * NPTS * CIN];            // feature point-major [b][n][c] (8 MB)
__device__ float g_xt[BS * NPTS * 4];              // coords point-major padded (512 KB)
__device__ float g_G[(size_t)CHUNK * KCONV];       // per-chunk flat feats (100 MB)
__device__ float g_pre[(size_t)COUT * PTOT];       // pre-BN output, channel-major (8 MB)
__device__ float g_scale[COUT];
__device__ float g_shift[COUT];

// ---------------------------------------------------------------------------
// Transpose feature (B, C, N) -> (b, n, c)
// ---------------------------------------------------------------------------
__global__ __launch_bounds__(256) void transpose_f(const float* __restrict__ f)
{
    int e = blockIdx.x * 256 + threadIdx.x;          // BS*CIN*NPTS = 2097152
    if (e >= BS * CIN * NPTS) return;
    int n = e & (NPTS - 1);
    int c = (e >> 13) & 63;
    int b = e >> 19;
    g_ft[(((size_t)(b << 13) + n) << 6) + c] = f[e];
}

// Transpose x (B, 3, N) -> (b, n, 4)
__global__ __launch_bounds__(256) void transpose_x(const float* __restrict__ x)
{
    int e = blockIdx.x * 256 + threadIdx.x;          // BS*3*NPTS = 98304
    if (e >= BS * 3 * NPTS) return;
    int b = e / (3 * NPTS);
    int r = e - b * 3 * NPTS;
    int d = r >> 13;
    int n = r & (NPTS - 1);
    g_xt[(((b << 13) + n) << 2) + d] = x[e];
}

// ---------------------------------------------------------------------------
// Per-point kernel: one block per point, 128 threads.
// Computes pe/x_feats, normalized perm, gathers neighbor features, and writes
// G[p_local][c*32+j] = sum_k feats[c][k] * perm[k][j]  (3072 floats / point).
// ---------------------------------------------------------------------------
__global__ __launch_bounds__(128) void point_kernel(
    int          pbase,
    const int*   __restrict__ neigh,
    const float* __restrict__ Bmat,
    const float* __restrict__ kern,
    const float* __restrict__ one_pad,
    const float* __restrict__ Wmlp,
    const float* __restrict__ bmlp)
{
    const int pl   = blockIdx.x;          // chunk-local point
    const int p    = pbase + pl;          // global point
    const int b    = p >> 13;
    const int t    = threadIdx.x;
    const int lane = t & 31;
    const int w    = t >> 5;

    __shared__ float s_pe[32][65];    // [k][f]  stride 65 -> conflict-free
    __shared__ float s_xf[32][36];    // x_feats [k][o], 16B-aligned rows
    __shared__ float s_perm[32][33];  // [k][j]
    __shared__ float s_f[32][64];     // gathered features [k][c]
    __shared__ float s_W[32][64];     // W_mlp [o][f]
    __shared__ float s_B[7][32];
    __shared__ float s_k[3][32];
    __shared__ float s_xn[32][4];
    __shared__ float s_rel[32][4];
    __shared__ float s_dis[32];
    __shared__ float s_inv[32];
    __shared__ int   s_idx[32];

    if (t < 32) s_idx[t] = neigh[(p << 5) + t];
    for (int i = t; i < 224;  i += 128) s_B[i >> 5][i & 31]    = Bmat[i];
    for (int i = t; i < 96;   i += 128) s_k[i >> 5][i & 31]    = kern[i];
    for (int i = t; i < 2048; i += 128) s_W[i >> 6][i & 63]    = Wmlp[i];
    for (int i = t; i < 1024; i += 128) s_perm[i >> 5][i & 31] = one_pad[i];
    __syncthreads();

    // gather neighbor features (coalesced 256B rows from point-major g_ft)
    for (int i = t; i < 512; i += 128) {
        int k = i >> 4, c4 = i & 15;
        float4 v = *((const float4*)(g_ft + (((size_t)(b << 13) + s_idx[k]) << 6) + (c4 << 2)));
        *((float4*)&s_f[k][c4 << 2]) = v;
    }
    // gather neighbor coords
    if (t < 32) {
        float4 v = *((const float4*)(g_xt + (((b << 13) + s_idx[t]) << 2)));
        s_xn[t][0] = v.x; s_xn[t][1] = v.y; s_xn[t][2] = v.z;
    }
    __syncthreads();

    // relative coords + distance (x_rep = neighbor 0)
    if (t < 32) {
        float r0 = s_xn[t][0] - s_xn[0][0];
        float r1 = s_xn[t][1] - s_xn[0][1];
        float r2 = s_xn[t][2] - s_xn[0][2];
        s_rel[t][0] = r0; s_rel[t][1] = r1; s_rel[t][2] = r2;
        s_dis[t] = sqrtf(fmaxf(r0 * r0 + r1 * r1 + r2 * r2, 1e-12f));
    }
    __syncthreads();

    // proj = (2*pi*[rep, rel, dis]) @ Bmat ; pe = [sin, cos]
    const float TWO_PI = 6.283185307179586f;
    const float rep0 = s_xn[0][0], rep1 = s_xn[0][1], rep2 = s_xn[0][2];
    #pragma unroll
    for (int it = 0; it < 8; it++) {
        int idx = t + it * 128;
        int k = idx >> 5, m = idx & 31;
        float acc = rep0 * s_B[0][m] + rep1 * s_B[1][m] + rep2 * s_B[2][m]
                  + s_rel[k][0] * s_B[3][m] + s_rel[k][1] * s_B[4][m] + s_rel[k][2] * s_B[5][m]
                  + s_dis[k] * s_B[6][m];
        acc *= TWO_PI;
        float sv, cv;
        __sincosf(acc, &sv, &cv);
        s_pe[k][m]      = sv;
        s_pe[k][32 + m] = cv;
    }
    __syncthreads();

    // x_feats[o][k] = sum_f pe[k][f] * W_mlp[o][f] + b_mlp[o]
    {
        const int o0 = w << 3;
        float acc[8];
        #pragma unroll
        for (int i = 0; i < 8; i++) acc[i] = bmlp[o0 + i];
        #pragma unroll
        for (int f = 0; f < 64; f++) {
            float pv = s_pe[lane][f];
            #pragma unroll
            for (int i = 0; i < 8; i++) acc[i] += pv * s_W[o0 + i][f];
        }
        *((float4*)&s_xf[lane][o0])     = make_float4(acc[0], acc[1], acc[2], acc[3]);
        *((float4*)&s_xf[lane][o0 + 4]) = make_float4(acc[4], acc[5], acc[6], acc[7]);
    }

    // perm[k][j] = relu(x_rel[k] . kernels[:,j] + one_padding[k][j])
    #pragma unroll
    for (int it = 0; it < 8; it++) {
        int idx = t + it * 128;
        int k = idx >> 5, j = idx & 31;
        float v = s_perm[k][j] + s_rel[k][0] * s_k[0][j]
                               + s_rel[k][1] * s_k[1][j]
                               + s_rel[k][2] * s_k[2][j];
        s_perm[k][j] = fmaxf(v, 0.0f);
    }
    __syncthreads();
    if (t < 32) {
        float s = 0.f;
        #pragma unroll
        for (int k = 0; k < 32; k++) s += s_perm[k][t];
        s_inv[t] = 1.0f / (s + 1e-6f);
    }
    __syncthreads();
    #pragma unroll
    for (int it = 0; it < 8; it++) {
        int idx = t + it * 128;
        int k = idx >> 5, j = idx & 31;
        s_perm[k][j] *= s_inv[j];
    }
    __syncthreads();

    // G[c][j] = sum_k feats[c][k] * perm[k][j]
    // thread owns column j = lane; perm column in 32 regs; broadcast LDS.128 on c.
    float pr[32];
    #pragma unroll
    for (int k = 0; k < 32; k++) pr[k] = s_perm[k][lane];

    float* gp = g_G + (size_t)pl * KCONV + lane;
    #pragma unroll
    for (int q = 0; q < 6; q++) {
        int c0 = (q * 4 + w) * 4;   // uniform per warp, 0..92
        float a0 = 0.f, a1 = 0.f, a2 = 0.f, a3 = 0.f;
        if (c0 < 64) {
            #pragma unroll
            for (int k = 0; k < 32; k++) {
                float4 fv = *((const float4*)&s_f[k][c0]);
                a0 += fv.x * pr[k]; a1 += fv.y * pr[k];
                a2 += fv.z * pr[k]; a3 += fv.w * pr[k];
            }
        } else {
            #pragma unroll
            for (int k = 0; k < 32; k++) {
                float4 fv = *((const float4*)&s_xf[k][c0 - 64]);
                a0 += fv.x * pr[k]; a1 += fv.y * pr[k];
                a2 += fv.z * pr[k]; a3 += fv.w * pr[k];
            }
        }
        gp[(size_t)(c0 + 0) * 32] = a0;
        gp[(size_t)(c0 + 1) * 32] = a1;
        gp[(size_t)(c0 + 2) * 32] = a2;
        gp[(size_t)(c0 + 3) * 32] = a3;
    }
}

// ---------------------------------------------------------------------------
// GEMM: pre[o][pbase+pl] = sum_k G[pl][k] * W_conv[o][k] + b_conv[o]
// M=CHUNK, N=64, K=3072. 64x64 tile, 4x4 register blocking, reg prefetch
// double-buffer to hide LDG latency (1 block/SM during chunk phases).
// ---------------------------------------------------------------------------
__global__ __launch_bounds__(256) void gemm_kernel(
    int pbase, const float* __restrict__ Wconv, const float* __restrict__ bconv)
{
    __shared__ float As[32][68];   // [kk][point]
    __shared__ float Ws[32][68];   // [kk][out]

    const int t  = threadIdx.x;
    const int tx = t & 15;         // out quad
    const int ty = t >> 4;         // point quad
    const int pl0 = blockIdx.x * 64;

    float acc[4][4];
    #pragma unroll
    for (int i = 0; i < 4; i++)
        #pragma unroll
        for (int j = 0; j < 4; j++) acc[i][j] = 0.f;

    const int kk = t & 31;
    const int r  = t >> 5;         // 0..7

    // prefetch first K-tile into registers
    float pa[8], pw[8];
    #pragma unroll
    for (int rr = 0; rr < 8; rr++) {
        int pp = r + rr * 8;
        pa[rr] = g_G[(size_t)(pl0 + pp) * KCONV + kk];
        pw[rr] = Wconv[(size_t)pp * KCONV + kk];
    }

    for (int k0 = 0; k0 < KCONV; k0 += 32) {
        #pragma unroll
        for (int rr = 0; rr < 8; rr++) {
            int pp = r + rr * 8;
            As[kk][pp] = pa[rr];
            Ws[kk][pp] = pw[rr];
        }
        __syncthreads();

        if (k0 + 32 < KCONV) {
            #pragma unroll
            for (int rr = 0; rr < 8; rr++) {
                int pp = r + rr * 8;
                pa[rr] = g_G[(size_t)(pl0 + pp) * KCONV + k0 + 32 + kk];
                pw[rr] = Wconv[(size_t)pp * KCONV + k0 + 32 + kk];
            }
        }

        #pragma unroll
        for (int k2 = 0; k2 < 32; k2++) {
            float4 a  = *((const float4*)&As[k2][ty << 2]);
            float4 wv = *((const float4*)&Ws[k2][tx << 2]);
            acc[0][0] += a.x * wv.x; acc[0][1] += a.x * wv.y; acc[0][2] += a.x * wv.z; acc[0][3] += a.x * wv.w;
            acc[1][0] += a.y * wv.x; acc[1][1] += a.y * wv.y; acc[1][2] += a.y * wv.z; acc[1][3] += a.y * wv.w;
            acc[2][0] += a.z * wv.x; acc[2][1] += a.z * wv.y; acc[2][2] += a.z * wv.z; acc[2][3] += a.z * wv.w;
            acc[3][0] += a.w * wv.x; acc[3][1] += a.w * wv.y; acc[3][2] += a.w * wv.z; acc[3][3] += a.w * wv.w;
        }
        __syncthreads();
    }

    #pragma unroll
    for (int j = 0; j < 4; j++) {
        int o = (tx << 2) + j;
        float bb = bconv[o];
        float4 v = make_float4(acc[0][j] + bb, acc[1][j] + bb, acc[2][j] + bb, acc[3][j] + bb);
        *((float4*)&g_pre[(size_t)o * PTOT + pbase + pl0 + (ty << 2)]) = v;
    }
}

// ---------------------------------------------------------------------------
// Per-channel mean/var over 32768 points (deterministic tree reduction).
// ---------------------------------------------------------------------------
__global__ __launch_bounds__(256) void stats_kernel(
    const float* __restrict__ gamma, const float* __restrict__ beta)
{
    const int o = blockIdx.x;
    const int t = threadIdx.x;
    const float* row = g_pre + (size_t)o * PTOT;
    float s = 0.f, s2 = 0.f;
    for (int i = t; i < PTOT; i += 256) {
        float v = row[i];
        s += v; s2 += v * v;
    }
    __shared__ float rs[256], rs2[256];
    rs[t] = s; rs2[t] = s2;
    __syncthreads();
    for (int st = 128; st > 0; st >>= 1) {
        if (t < st) { rs[t] += rs[t + st]; rs2[t] += rs2[t + st]; }
        __syncthreads();
    }
    if (t == 0) {
        float mean = rs[0] * (1.0f / PTOT);
        float var  = rs2[0] * (1.0f / PTOT) - mean * mean;
        float inv  = rsqrtf(var + 1e-5f);
        float sc   = gamma[o] * inv;
        g_scale[o] = sc;
        g_shift[o] = beta[o] - mean * sc;
    }
}

// ---------------------------------------------------------------------------
// Normalize + write output (B, C_OUT, N)
// ---------------------------------------------------------------------------
__global__ __launch_bounds__(256) void norm_kernel(float* __restrict__ out)
{
    int e = blockIdx.x * 256 + threadIdx.x;     // 2097152
    if (e >= BS * COUT * NPTS) return;
    int n = e & (NPTS - 1);
    int o = (e >> 13) & 63;
    int b = e >> 19;
    float v = g_pre[(size_t)o * PTOT + (b << 13) + n];
    out[e] = v * g_scale[o] + g_shift[o];
}

// ---------------------------------------------------------------------------
extern "C" void kernel_launch(void* const* d_in, const int* in_sizes, int n_in,
                              void* d_out, int out_size)
{
    const float* x     = (const float*)d_in[0];
    const float* feat  = (const float*)d_in[1];
    const int*   neigh = (const int*)  d_in[2];
    const float* Bmat  = (const float*)d_in[3];
    const float* kern  = (const float*)d_in[4];
    const float* onep  = (const float*)d_in[5];
    const float* Wmlp  = (const float*)d_in[6];
    const float* bmlp  = (const float*)d_in[7];
    const float* Wconv = (const float*)d_in[8];
    const float* bconv = (const float*)d_in[9];
    const float* gamma = (const float*)d_in[10];
    const float* beta  = (const float*)d_in[11];
    float* out = (float*)d_out;

    transpose_f<<<(BS * CIN * NPTS + 255) / 256, 256>>>(feat);
    transpose_x<<<(BS * 3 * NPTS + 255) / 256, 256>>>(x);
    for (int c = 0; c < NCHUNK; c++) {
        point_kernel<<<CHUNK, 128>>>(c * CHUNK, neigh, Bmat, kern, onep, Wmlp, bmlp);
        gemm_kernel<<<CHUNK / 64, 256>>>(c * CHUNK, Wconv, bconv);
    }
    stats_kernel<<<COUT, 256>>>(gamma, beta);
    norm_kernel<<<(BS * COUT * NPTS + 255) / 256, 256>>>(out);
}

// round 5
// speedup vs baseline: 1.0028x; 1.0028x over previous
#include <cuda_runtime.h>
#include <math.h>

#define BS     4
#define NPTS   8192
#define KNB    32
#define CIN    64
#define CX     32
#define CF     96
#define COUT   64
#define KCONV  3072
#define PTOT   32768
#define CHUNK  8192
#define NCHUNK (PTOT / CHUNK)
#define KSPLIT 4
#define KPART  (KCONV / KSPLIT)   // 768
#define PPB    4                  // points per block in point_kernel

// ---- device scratch (allocation-free: static __device__ globals) ----
__device__ float g_ft[BS * NPTS * CIN];                  // feature point-major (8 MB)
__device__ float g_xt[BS * NPTS * 4];                    // coords point-major (512 KB)
__device__ float g_G[(size_t)CHUNK * KCONV];             // per-chunk flat feats (100 MB)
__device__ float g_part[(size_t)KSPLIT * COUT * PTOT];   // K-split partials (32 MB)
__device__ float g_pre[(size_t)COUT * PTOT];             // combined pre-BN (8 MB)
__device__ float g_scale[COUT];
__device__ float g_shift[COUT];

// ---------------------------------------------------------------------------
__global__ __launch_bounds__(256) void transpose_f(const float* __restrict__ f)
{
    int e = blockIdx.x * 256 + threadIdx.x;
    if (e >= BS * CIN * NPTS) return;
    int n = e & (NPTS - 1);
    int c = (e >> 13) & 63;
    int b = e >> 19;
    g_ft[(((size_t)(b << 13) + n) << 6) + c] = f[e];
}

__global__ __launch_bounds__(256) void transpose_x(const float* __restrict__ x)
{
    int e = blockIdx.x * 256 + threadIdx.x;
    if (e >= BS * 3 * NPTS) return;
    int b = e / (3 * NPTS);
    int r = e - b * 3 * NPTS;
    int d = r >> 13;
    int n = r & (NPTS - 1);
    g_xt[(((b << 13) + n) << 2) + d] = x[e];
}

// ---------------------------------------------------------------------------
// Per-point kernel: 128 threads, PPB points per block (constants loaded once).
// ---------------------------------------------------------------------------
__global__ __launch_bounds__(128) void point_kernel(
    int          pbase,
    const int*   __restrict__ neigh,
    const float* __restrict__ Bmat,
    const float* __restrict__ kern,
    const float* __restrict__ one_pad,
    const float* __restrict__ Wmlp,
    const float* __restrict__ bmlp)
{
    const int t    = threadIdx.x;
    const int lane = t & 31;
    const int w    = t >> 5;

    __shared__ float s_pe[32][65];    // [k][f]
    __shared__ float s_xf[32][36];    // x_feats [k][o]
    __shared__ float s_perm[32][33];  // [k][j]
    __shared__ float s_op[32][33];    // one_padding (persistent)
    __shared__ float s_f[32][64];     // gathered features [k][c]
    __shared__ float s_W[32][64];     // W_mlp [o][f] (persistent)
    __shared__ float s_B[7][32];
    __shared__ float s_k[3][32];
    __shared__ float s_bm[32];
    __shared__ float s_xn[32][4];
    __shared__ float s_rel[32][4];
    __shared__ float s_dis[32];
    __shared__ float s_inv[32];
    __shared__ int   s_idx[32];

    // persistent constants, loaded once per block
    for (int i = t; i < 224;  i += 128) s_B[i >> 5][i & 31]  = Bmat[i];
    for (int i = t; i < 96;   i += 128) s_k[i >> 5][i & 31]  = kern[i];
    for (int i = t; i < 2048; i += 128) s_W[i >> 6][i & 63]  = Wmlp[i];
    for (int i = t; i < 1024; i += 128) s_op[i >> 5][i & 31] = one_pad[i];
    if (t < 32) s_bm[t] = bmlp[t];

    const float TWO_PI = 6.283185307179586f;

    for (int ip = 0; ip < PPB; ip++) {
        const int pl = blockIdx.x * PPB + ip;    // chunk-local point
        const int p  = pbase + pl;               // global point
        const int b  = p >> 13;

        __syncthreads();   // previous iteration consumers done / constants ready

        if (t < 32) s_idx[t] = neigh[(p << 5) + t];
        // init perm from one_padding
        #pragma unroll
        for (int it = 0; it < 8; it++) {
            int idx = t + it * 128;
            s_perm[idx >> 5][idx & 31] = s_op[idx >> 5][idx & 31];
        }
        __syncthreads();

        // gather neighbor features (coalesced 256B rows)
        for (int i = t; i < 512; i += 128) {
            int k = i >> 4, c4 = i & 15;
            float4 v = *((const float4*)(g_ft + (((size_t)(b << 13) + s_idx[k]) << 6) + (c4 << 2)));
            *((float4*)&s_f[k][c4 << 2]) = v;
        }
        if (t < 32) {
            float4 v = *((const float4*)(g_xt + (((b << 13) + s_idx[t]) << 2)));
            s_xn[t][0] = v.x; s_xn[t][1] = v.y; s_xn[t][2] = v.z;
        }
        __syncthreads();

        if (t < 32) {
            float r0 = s_xn[t][0] - s_xn[0][0];
            float r1 = s_xn[t][1] - s_xn[0][1];
            float r2 = s_xn[t][2] - s_xn[0][2];
            s_rel[t][0] = r0; s_rel[t][1] = r1; s_rel[t][2] = r2;
            s_dis[t] = sqrtf(fmaxf(r0 * r0 + r1 * r1 + r2 * r2, 1e-12f));
        }
        __syncthreads();

        // proj = (2*pi*[rep, rel, dis]) @ Bmat ; pe = [sin, cos]
        const float rep0 = s_xn[0][0], rep1 = s_xn[0][1], rep2 = s_xn[0][2];
        #pragma unroll
        for (int it = 0; it < 8; it++) {
            int idx = t + it * 128;
            int k = idx >> 5, m = idx & 31;
            float acc = rep0 * s_B[0][m] + rep1 * s_B[1][m] + rep2 * s_B[2][m]
                      + s_rel[k][0] * s_B[3][m] + s_rel[k][1] * s_B[4][m] + s_rel[k][2] * s_B[5][m]
                      + s_dis[k] * s_B[6][m];
            acc *= TWO_PI;
            float sv, cv;
            __sincosf(acc, &sv, &cv);
            s_pe[k][m]      = sv;
            s_pe[k][32 + m] = cv;
        }
        __syncthreads();

        // x_feats[o][k] = pe[k][:] . W_mlp[o][:] + b_mlp[o]   (warp w: 8 o's)
        {
            const int o0 = w << 3;
            float acc[8];
            #pragma unroll
            for (int i = 0; i < 8; i++) acc[i] = s_bm[o0 + i];
            #pragma unroll
            for (int f = 0; f < 64; f++) {
                float pv = s_pe[lane][f];
                #pragma unroll
                for (int i = 0; i < 8; i++) acc[i] += pv * s_W[o0 + i][f];
            }
            *((float4*)&s_xf[lane][o0])     = make_float4(acc[0], acc[1], acc[2], acc[3]);
            *((float4*)&s_xf[lane][o0 + 4]) = make_float4(acc[4], acc[5], acc[6], acc[7]);
        }

        // perm[k][j] = relu(x_rel[k] . kernels[:,j] + one_padding[k][j])
        #pragma unroll
        for (int it = 0; it < 8; it++) {
            int idx = t + it * 128;
            int k = idx >> 5, j = idx & 31;
            float v = s_perm[k][j] + s_rel[k][0] * s_k[0][j]
                                   + s_rel[k][1] * s_k[1][j]
                                   + s_rel[k][2] * s_k[2][j];
            s_perm[k][j] = fmaxf(v, 0.0f);
        }
        __syncthreads();
        if (t < 32) {
            float s = 0.f;
            #pragma unroll
            for (int k = 0; k < 32; k++) s += s_perm[k][t];
            s_inv[t] = 1.0f / (s + 1e-6f);
        }
        __syncthreads();
        #pragma unroll
        for (int it = 0; it < 8; it++) {
            int idx = t + it * 128;
            int k = idx >> 5, j = idx & 31;
            s_perm[k][j] *= s_inv[j];
        }
        __syncthreads();

        // G[c][j] = sum_k feats[c][k] * perm[k][j]
        float pr[32];
        #pragma unroll
        for (int k = 0; k < 32; k++) pr[k] = s_perm[k][lane];

        float* gp = g_G + (size_t)pl * KCONV + lane;
        #pragma unroll
        for (int q = 0; q < 6; q++) {
            int c0 = (q * 4 + w) * 4;   // uniform per warp, 0..92
            float a0 = 0.f, a1 = 0.f, a2 = 0.f, a3 = 0.f;
            if (c0 < 64) {
                #pragma unroll
                for (int k = 0; k < 32; k++) {
                    float4 fv = *((const float4*)&s_f[k][c0]);
                    a0 += fv.x * pr[k]; a1 += fv.y * pr[k];
                    a2 += fv.z * pr[k]; a3 += fv.w * pr[k];
                }
            } else {
                #pragma unroll
                for (int k = 0; k < 32; k++) {
                    float4 fv = *((const float4*)&s_xf[k][c0 - 64]);
                    a0 += fv.x * pr[k]; a1 += fv.y * pr[k];
                    a2 += fv.z * pr[k]; a3 += fv.w * pr[k];
                }
            }
            gp[(size_t)(c0 + 0) * 32] = a0;
            gp[(size_t)(c0 + 1) * 32] = a1;
            gp[(size_t)(c0 + 2) * 32] = a2;
            gp[(size_t)(c0 + 3) * 32] = a3;
        }
    }
}

// ---------------------------------------------------------------------------
// GEMM (K-split): part[h][o][p] = sum_{k in h-th K/4} G[pl][k] * Wconv[o][k]
// Tile 64 pts x 64 outs, 128 threads, micro-tile 4x8, reg-prefetch double buf.
// grid = (CHUNK/64, KSPLIT)
// ---------------------------------------------------------------------------
__global__ __launch_bounds__(128) void gemm_kernel(
    int pbase, const float* __restrict__ Wconv)
{
    __shared__ float As[32][68];   // [kk][point]
    __shared__ float Ws[32][68];   // [kk][out]

    const int t   = threadIdx.x;
    const int tx  = t & 7;          // out octet: o = tx*8 + j
    const int ty  = t >> 3;         // point quad: p = ty*4 + i  (ty 0..15)
    const int pl0 = blockIdx.x * 64;
    const int h   = blockIdx.y;
    const int kb  = h * KPART;

    float acc[4][8];
    #pragma unroll
    for (int i = 0; i < 4; i++)
        #pragma unroll
        for (int j = 0; j < 8; j++) acc[i][j] = 0.f;

    const int kk = t & 31;
    const int r  = t >> 5;          // 0..3

    const float* Ab = g_G   + (size_t)pl0 * KCONV + kb + kk;
    const float* Wb = Wconv + kb + kk;

    float pa[16], pw[16];
    #pragma unroll
    for (int rr = 0; rr < 16; rr++) {
        int pp = r + rr * 4;
        pa[rr] = Ab[(size_t)pp * KCONV];
        pw[rr] = Wb[(size_t)pp * KCONV];
    }

    for (int k0 = 0; k0 < KPART; k0 += 32) {
        #pragma unroll
        for (int rr = 0; rr < 16; rr++) {
            int pp = r + rr * 4;
            As[kk][pp] = pa[rr];
            Ws[kk][pp] = pw[rr];
        }
        __syncthreads();

        if (k0 + 32 < KPART) {
            #pragma unroll
            for (int rr = 0; rr < 16; rr++) {
                int pp = r + rr * 4;
                pa[rr] = Ab[(size_t)pp * KCONV + k0 + 32];
                pw[rr] = Wb[(size_t)pp * KCONV + k0 + 32];
            }
        }

        #pragma unroll
        for (int k2 = 0; k2 < 32; k2++) {
            float4 a  = *((const float4*)&As[k2][ty << 2]);
            float4 w0 = *((const float4*)&Ws[k2][tx << 3]);
            float4 w1 = *((const float4*)&Ws[k2][(tx << 3) + 4]);
            float av[4] = {a.x, a.y, a.z, a.w};
            float wv[8] = {w0.x, w0.y, w0.z, w0.w, w1.x, w1.y, w1.z, w1.w};
            #pragma unroll
            for (int i = 0; i < 4; i++)
                #pragma unroll
                for (int j = 0; j < 8; j++)
                    acc[i][j] += av[i] * wv[j];
        }
        __syncthreads();
    }

    #pragma unroll
    for (int j = 0; j < 8; j++) {
        int o = (tx << 3) + j;
        float4 v = make_float4(acc[0][j], acc[1][j], acc[2][j], acc[3][j]);
        *((float4*)&g_part[(((size_t)h * COUT + o) * PTOT) + pbase + pl0 + (ty << 2)]) = v;
    }
}

// ---------------------------------------------------------------------------
// Combine K-split partials + bias, per-channel mean/var (deterministic).
// ---------------------------------------------------------------------------
__global__ __launch_bounds__(256) void stats_kernel(
    const float* __restrict__ bconv,
    const float* __restrict__ gamma, const float* __restrict__ beta)
{
    const int o = blockIdx.x;
    const int t = threadIdx.x;
    const float4* r0 = (const float4*)(g_part + ((size_t)0 * COUT + o) * PTOT);
    const float4* r1 = (const float4*)(g_part + ((size_t)1 * COUT + o) * PTOT);
    const float4* r2 = (const float4*)(g_part + ((size_t)2 * COUT + o) * PTOT);
    const float4* r3 = (const float4*)(g_part + ((size_t)3 * COUT + o) * PTOT);
    float4*       pr = (float4*)(g_pre + (size_t)o * PTOT);
    const float bb = bconv[o];

    float s = 0.f, s2 = 0.f;
    for (int i = t; i < PTOT / 4; i += 256) {
        float4 a = r0[i], b = r1[i], c = r2[i], d = r3[i];
        float4 v;
        v.x = a.x + b.x + c.x + d.x + bb;
        v.y = a.y + b.y + c.y + d.y + bb;
        v.z = a.z + b.z + c.z + d.z + bb;
        v.w = a.w + b.w + c.w + d.w + bb;
        pr[i] = v;
        s  += v.x + v.y + v.z + v.w;
        s2 += v.x * v.x + v.y * v.y + v.z * v.z + v.w * v.w;
    }
    __shared__ float rs[256], rs2[256];
    rs[t] = s; rs2[t] = s2;
    __syncthreads();
    for (int st = 128; st > 0; st >>= 1) {
        if (t < st) { rs[t] += rs[t + st]; rs2[t] += rs2[t + st]; }
        __syncthreads();
    }
    if (t == 0) {
        float mean = rs[0] * (1.0f / PTOT);
        float var  = rs2[0] * (1.0f / PTOT) - mean * mean;
        float inv  = rsqrtf(var + 1e-5f);
        float sc   = gamma[o] * inv;
        g_scale[o] = sc;
        g_shift[o] = beta[o] - mean * sc;
    }
}

// ---------------------------------------------------------------------------
// Normalize + write output (B, C_OUT, N), vectorized.
// ---------------------------------------------------------------------------
__global__ __launch_bounds__(256) void norm_kernel(float* __restrict__ out)
{
    int e = blockIdx.x * 256 + threadIdx.x;     // elements/4 = 524288
    if (e >= BS * COUT * NPTS / 4) return;
    int nq = e & (NPTS / 4 - 1);
    int o  = (e >> 11) & 63;
    int b  = e >> 17;
    float4 v = *((const float4*)(g_pre + (size_t)o * PTOT + (b << 13)) + nq);
    float sc = g_scale[o], sh = g_shift[o];
    float4 r = make_float4(v.x * sc + sh, v.y * sc + sh, v.z * sc + sh, v.w * sc + sh);
    *((float4*)out + e) = r;
}

// ---------------------------------------------------------------------------
extern "C" void kernel_launch(void* const* d_in, const int* in_sizes, int n_in,
                              void* d_out, int out_size)
{
    const float* x     = (const float*)d_in[0];
    const float* feat  = (const float*)d_in[1];
    const int*   neigh = (const int*)  d_in[2];
    const float* Bmat  = (const float*)d_in[3];
    const float* kern  = (const float*)d_in[4];
    const float* onep  = (const float*)d_in[5];
    const float* Wmlp  = (const float*)d_in[6];
    const float* bmlp  = (const float*)d_in[7];
    const float* Wconv = (const float*)d_in[8];
    const float* bconv = (const float*)d_in[9];
    const float* gamma = (const float*)d_in[10];
    const float* beta  = (const float*)d_in[11];
    float* out = (float*)d_out;

    transpose_f<<<(BS * CIN * NPTS + 255) / 256, 256>>>(feat);
    transpose_x<<<(BS * 3 * NPTS + 255) / 256, 256>>>(x);
    for (int c = 0; c < NCHUNK; c++) {
        point_kernel<<<CHUNK / PPB, 128>>>(c * CHUNK, neigh, Bmat, kern, onep, Wmlp, bmlp);
        gemm_kernel<<<dim3(CHUNK / 64, KSPLIT), 128>>>(c * CHUNK, Wconv);
    }
    stats_kernel<<<COUT, 256>>>(bconv, gamma, beta);
    norm_kernel<<<(BS * COUT * NPTS / 4 + 255) / 256, 256>>>(out);
}

// round 8
// speedup vs baseline: 1.3694x; 1.3656x over previous
#include <cuda_runtime.h>
#include <cuda_bf16.h>
#include <math.h>
#include <stdint.h>

#define BS     4
#define NPTS   8192
#define KNB    32
#define CIN    64
#define CX     32
#define CF     96
#define COUT   64
#define KCONV  3072
#define PTOT   32768
#define CHUNK  8192
#define NCHUNK (PTOT / CHUNK)
#define KSPLIT 4
#define KPART  (KCONV / KSPLIT)   // 768
#define PPB    4                  // points per block in point_kernel

// ---- device scratch (allocation-free: static __device__ globals) ----
__device__ float g_ft[BS * NPTS * CIN];                  // feature point-major (8 MB)
__device__ float g_xt[BS * NPTS * 4];                    // coords point-major (512 KB)
__device__ float g_G[(size_t)CHUNK * KCONV];             // per-chunk flat feats (100 MB)
__device__ float g_part[(size_t)KSPLIT * COUT * PTOT];   // K-split partials (32 MB)
__device__ float g_pre[(size_t)COUT * PTOT];             // combined pre-BN (8 MB)
__device__ float g_scale[COUT];
__device__ float g_shift[COUT];
__device__ __nv_bfloat16 g_Whi[(size_t)COUT * KCONV];    // W split hi (384 KB)
__device__ __nv_bfloat16 g_Wlo[(size_t)COUT * KCONV];    // W split lo (384 KB)

// ===========================================================================
// PTX helpers: ldmatrix + warp-level bf16 mma (PTX ISA 7.x, valid on compute_100)
// ===========================================================================
__device__ __forceinline__ uint32_t smem_u32(const void* p) {
    uint32_t a;
    asm("{ .reg .u64 t; cvta.to.shared.u64 t, %1; cvt.u32.u64 %0, t; }" : "=r"(a) : "l"(p));
    return a;
}
__device__ __forceinline__ void ldsm4(uint32_t* r, uint32_t addr) {
    asm volatile("ldmatrix.sync.aligned.m8n8.x4.shared.b16 {%0,%1,%2,%3}, [%4];"
                 : "=r"(r[0]), "=r"(r[1]), "=r"(r[2]), "=r"(r[3]) : "r"(addr));
}
__device__ __forceinline__ void mma_bf16(float* d, const uint32_t* a, const uint32_t* b) {
    asm volatile(
        "mma.sync.aligned.m16n8k16.row.col.f32.bf16.bf16.f32 "
        "{%0,%1,%2,%3}, {%4,%5,%6,%7}, {%8,%9}, {%0,%1,%2,%3};"
        : "+f"(d[0]), "+f"(d[1]), "+f"(d[2]), "+f"(d[3])
        : "r"(a[0]), "r"(a[1]), "r"(a[2]), "r"(a[3]), "r"(b[0]), "r"(b[1]));
}
__device__ __forceinline__ uint32_t bfpack(float a, float b) {
    __nv_bfloat16 ha = __float2bfloat16_rn(a), hb = __float2bfloat16_rn(b);
    return ((uint32_t)__bfloat16_as_ushort(hb) << 16) | (uint32_t)__bfloat16_as_ushort(ha);
}

// ---------------------------------------------------------------------------
__global__ __launch_bounds__(256) void prep_w(const float* __restrict__ Wconv)
{
    int e = blockIdx.x * 256 + threadIdx.x;          // COUT*KCONV = 196608
    if (e >= COUT * KCONV) return;
    float w = Wconv[e];
    __nv_bfloat16 hi = __float2bfloat16_rn(w);
    g_Whi[e] = hi;
    g_Wlo[e] = __float2bfloat16_rn(w - __bfloat162float(hi));
}

// ---------------------------------------------------------------------------
__global__ __launch_bounds__(256) void transpose_f(const float* __restrict__ f)
{
    int e = blockIdx.x * 256 + threadIdx.x;
    if (e >= BS * CIN * NPTS) return;
    int n = e & (NPTS - 1);
    int c = (e >> 13) & 63;
    int b = e >> 19;
    g_ft[(((size_t)(b << 13) + n) << 6) + c] = f[e];
}

__global__ __launch_bounds__(256) void transpose_x(const float* __restrict__ x)
{
    int e = blockIdx.x * 256 + threadIdx.x;
    if (e >= BS * 3 * NPTS) return;
    int b = e / (3 * NPTS);
    int r = e - b * 3 * NPTS;
    int d = r >> 13;
    int n = r & (NPTS - 1);
    g_xt[(((b << 13) + n) << 2) + d] = x[e];
}

// ---------------------------------------------------------------------------
// Per-point kernel (unchanged, known-good)
// ---------------------------------------------------------------------------
__global__ __launch_bounds__(128) void point_kernel(
    int          pbase,
    const int*   __restrict__ neigh,
    const float* __restrict__ Bmat,
    const float* __restrict__ kern,
    const float* __restrict__ one_pad,
    const float* __restrict__ Wmlp,
    const float* __restrict__ bmlp)
{
    const int t    = threadIdx.x;
    const int lane = t & 31;
    const int w    = t >> 5;

    __shared__ float s_pe[32][65];
    __shared__ float s_xf[32][36];
    __shared__ float s_perm[32][33];
    __shared__ float s_op[32][33];
    __shared__ float s_f[32][64];
    __shared__ float s_W[32][64];
    __shared__ float s_B[7][32];
    __shared__ float s_k[3][32];
    __shared__ float s_bm[32];
    __shared__ float s_xn[32][4];
    __shared__ float s_rel[32][4];
    __shared__ float s_dis[32];
    __shared__ float s_inv[32];
    __shared__ int   s_idx[32];

    for (int i = t; i < 224;  i += 128) s_B[i >> 5][i & 31]  = Bmat[i];
    for (int i = t; i < 96;   i += 128) s_k[i >> 5][i & 31]  = kern[i];
    for (int i = t; i < 2048; i += 128) s_W[i >> 6][i & 63]  = Wmlp[i];
    for (int i = t; i < 1024; i += 128) s_op[i >> 5][i & 31] = one_pad[i];
    if (t < 32) s_bm[t] = bmlp[t];

    const float TWO_PI = 6.283185307179586f;

    for (int ip = 0; ip < PPB; ip++) {
        const int pl = blockIdx.x * PPB + ip;
        const int p  = pbase + pl;
        const int b  = p >> 13;

        __syncthreads();

        if (t < 32) s_idx[t] = neigh[(p << 5) + t];
        __syncthreads();

        for (int i = t; i < 512; i += 128) {
            int k = i >> 4, c4 = i & 15;
            float4 v = *((const float4*)(g_ft + (((size_t)(b << 13) + s_idx[k]) << 6) + (c4 << 2)));
            *((float4*)&s_f[k][c4 << 2]) = v;
        }
        if (t < 32) {
            float4 v = *((const float4*)(g_xt + (((b << 13) + s_idx[t]) << 2)));
            s_xn[t][0] = v.x; s_xn[t][1] = v.y; s_xn[t][2] = v.z;
        }
        __syncthreads();

        if (t < 32) {
            float r0 = s_xn[t][0] - s_xn[0][0];
            float r1 = s_xn[t][1] - s_xn[0][1];
            float r2 = s_xn[t][2] - s_xn[0][2];
            s_rel[t][0] = r0; s_rel[t][1] = r1; s_rel[t][2] = r2;
            s_dis[t] = sqrtf(fmaxf(r0 * r0 + r1 * r1 + r2 * r2, 1e-12f));
        }
        __syncthreads();

        const float rep0 = s_xn[0][0], rep1 = s_xn[0][1], rep2 = s_xn[0][2];
        #pragma unroll
        for (int it = 0; it < 8; it++) {
            int idx = t + it * 128;
            int k = idx >> 5, m = idx & 31;
            float acc = rep0 * s_B[0][m] + rep1 * s_B[1][m] + rep2 * s_B[2][m]
                      + s_rel[k][0] * s_B[3][m] + s_rel[k][1] * s_B[4][m] + s_rel[k][2] * s_B[5][m]
                      + s_dis[k] * s_B[6][m];
            acc *= TWO_PI;
            float sv, cv;
            __sincosf(acc, &sv, &cv);
            s_pe[k][m]      = sv;
            s_pe[k][32 + m] = cv;
        }
        __syncthreads();

        {
            const int o0 = w << 3;
            float acc[8];
            #pragma unroll
            for (int i = 0; i < 8; i++) acc[i] = s_bm[o0 + i];
            #pragma unroll
            for (int f = 0; f < 64; f++) {
                float pv = s_pe[lane][f];
                #pragma unroll
                for (int i = 0; i < 8; i++) acc[i] += pv * s_W[o0 + i][f];
            }
            *((float4*)&s_xf[lane][o0])     = make_float4(acc[0], acc[1], acc[2], acc[3]);
            *((float4*)&s_xf[lane][o0 + 4]) = make_float4(acc[4], acc[5], acc[6], acc[7]);
        }

        #pragma unroll
        for (int it = 0; it < 8; it++) {
            int idx = t + it * 128;
            int k = idx >> 5, j = idx & 31;
            float v = s_op[k][j] + s_rel[k][0] * s_k[0][j]
                                 + s_rel[k][1] * s_k[1][j]
                                 + s_rel[k][2] * s_k[2][j];
            s_perm[k][j] = fmaxf(v, 0.0f);
        }
        __syncthreads();
        if (t < 32) {
            float s = 0.f;
            #pragma unroll
            for (int k = 0; k < 32; k++) s += s_perm[k][t];
            s_inv[t] = 1.0f / (s + 1e-6f);
        }
        __syncthreads();
        #pragma unroll
        for (int it = 0; it < 8; it++) {
            int idx = t + it * 128;
            int k = idx >> 5, j = idx & 31;
            s_perm[k][j] *= s_inv[j];
        }
        __syncthreads();

        float pr[32];
        #pragma unroll
        for (int k = 0; k < 32; k++) pr[k] = s_perm[k][lane];

        float* gp = g_G + (size_t)pl * KCONV + lane;
        #pragma unroll
        for (int q = 0; q < 6; q++) {
            int c0 = (q * 4 + w) * 4;
            float a0 = 0.f, a1 = 0.f, a2 = 0.f, a3 = 0.f;
            if (c0 < 64) {
                #pragma unroll
                for (int k = 0; k < 32; k++) {
                    float4 fv = *((const float4*)&s_f[k][c0]);
                    a0 += fv.x * pr[k]; a1 += fv.y * pr[k];
                    a2 += fv.z * pr[k]; a3 += fv.w * pr[k];
                }
            } else {
                #pragma unroll
                for (int k = 0; k < 32; k++) {
                    float4 fv = *((const float4*)&s_xf[k][c0 - 64]);
                    a0 += fv.x * pr[k]; a1 += fv.y * pr[k];
                    a2 += fv.z * pr[k]; a3 += fv.w * pr[k];
                }
            }
            gp[(size_t)(c0 + 0) * 32] = a0;
            gp[(size_t)(c0 + 1) * 32] = a1;
            gp[(size_t)(c0 + 2) * 32] = a2;
            gp[(size_t)(c0 + 3) * 32] = a3;
        }
    }
}

// ---------------------------------------------------------------------------
// bf16 3-term split GEMM via warp-level mma.sync (HMMA).
// part[kh][o][p] = sum_{k in kh-th K/4} G[pl][k] * Wconv[o][k]
// CTA: 128 threads (4 warps), M=128 points x N=64 outs, K=768.
// grid = (CHUNK/128, KSPLIT).
// Dynamic smem (rows padded to 72 bf16 = 144B -> conflict-free ldmatrix):
//   [0]      Ahi 128x72 bf16 (18432 B)
//   [18432]  Alo 128x72 bf16 (18432 B)
//   [36864]  Whi  64x72 bf16 ( 9216 B)
//   [46080]  Wlo  64x72 bf16 ( 9216 B)   total 55296 B
// Epilogue staging aliases [0..33792): float stg[64][132].
// ---------------------------------------------------------------------------
#define OFF_AHI 0
#define OFF_ALO 18432
#define OFF_WHI 36864
#define OFF_WLO 46080
#define GEMM_SMEM 55296
#define APITCH 72
#define SPITCH 132

__global__ __launch_bounds__(128) void gemm_kernel(int pbase)
{
    extern __shared__ char smem[];
    __nv_bfloat16* Ahi = (__nv_bfloat16*)(smem + OFF_AHI);
    __nv_bfloat16* Alo = (__nv_bfloat16*)(smem + OFF_ALO);
    __nv_bfloat16* Whs = (__nv_bfloat16*)(smem + OFF_WHI);
    __nv_bfloat16* Wls = (__nv_bfloat16*)(smem + OFF_WLO);
    float*         stg = (float*)smem;
    const uint32_t sb  = smem_u32(smem);

    const int t    = threadIdx.x;
    const int lane = t & 31;
    const int w    = t >> 5;
    const int pl0  = blockIdx.x * 128;
    const int kh   = blockIdx.y;
    const int kb   = kh * KPART;

    float acc[2][8][4];
    #pragma unroll
    for (int mt = 0; mt < 2; mt++)
        #pragma unroll
        for (int nt = 0; nt < 8; nt++)
            #pragma unroll
            for (int i = 0; i < 4; i++) acc[mt][nt][i] = 0.f;

    const int wrow  = t >> 1;      // W tile row 0..63
    const int whalf = t & 1;       // 32-bf16 half

    // ldmatrix lane address components (element offsets)
    const int a_row  = (lane & 15);
    const int a_col  = (lane >> 4) << 3;                         // 0 or 8
    const int b_n    = (lane & 7) + (((lane >> 4) & 1) << 3);    // 0..15 within np group
    const int b_koff = ((lane >> 3) & 1) << 3;                   // 0 or 8

    for (int kc = 0; kc < KPART / 64; kc++) {
        // ---- convert A chunk: row t, 64 fp32 -> bf16 hi/lo
        {
            const float* src = g_G + (size_t)(pl0 + t) * KCONV + kb + kc * 64;
            #pragma unroll
            for (int j = 0; j < 8; j++) {
                float4 f0 = *((const float4*)(src + j * 8));
                float4 f1 = *((const float4*)(src + j * 8 + 4));
                float v[8] = {f0.x, f0.y, f0.z, f0.w, f1.x, f1.y, f1.z, f1.w};
                float r[8];
                #pragma unroll
                for (int i = 0; i < 8; i++) {
                    __nv_bfloat16 hb = __float2bfloat16_rn(v[i]);
                    r[i] = v[i] - __bfloat162float(hb);
                }
                uint4 hv, lv;
                hv.x = bfpack(v[0], v[1]); hv.y = bfpack(v[2], v[3]);
                hv.z = bfpack(v[4], v[5]); hv.w = bfpack(v[6], v[7]);
                lv.x = bfpack(r[0], r[1]); lv.y = bfpack(r[2], r[3]);
                lv.z = bfpack(r[4], r[5]); lv.w = bfpack(r[6], r[7]);
                *((uint4*)(Ahi + t * APITCH + j * 8)) = hv;
                *((uint4*)(Alo + t * APITCH + j * 8)) = lv;
            }
        }
        // ---- copy W chunk (pre-split bf16)
        {
            size_t off = (size_t)wrow * KCONV + kb + kc * 64 + whalf * 32;
            const uint4* wh = (const uint4*)(g_Whi + off);
            const uint4* wl = (const uint4*)(g_Wlo + off);
            #pragma unroll
            for (int i = 0; i < 4; i++) {
                *((uint4*)(Whs + wrow * APITCH + whalf * 32 + i * 8)) = wh[i];
                *((uint4*)(Wls + wrow * APITCH + whalf * 32 + i * 8)) = wl[i];
            }
        }
        __syncthreads();

        #pragma unroll
        for (int s = 0; s < 4; s++) {
            const int k0 = s * 16;
            uint32_t ah[2][4], al[2][4];
            #pragma unroll
            for (int mt = 0; mt < 2; mt++) {
                int row = w * 32 + mt * 16 + a_row;
                uint32_t addr = sb + OFF_AHI + (uint32_t)(row * APITCH + a_col + k0) * 2;
                ldsm4(ah[mt], addr);
                addr = sb + OFF_ALO + (uint32_t)(row * APITCH + a_col + k0) * 2;
                ldsm4(al[mt], addr);
            }
            #pragma unroll
            for (int np = 0; np < 4; np++) {
                int n = np * 16 + b_n;
                uint32_t bh[4], bl[4];
                uint32_t addr = sb + OFF_WHI + (uint32_t)(n * APITCH + k0 + b_koff) * 2;
                ldsm4(bh, addr);
                addr = sb + OFF_WLO + (uint32_t)(n * APITCH + k0 + b_koff) * 2;
                ldsm4(bl, addr);
                #pragma unroll
                for (int mt = 0; mt < 2; mt++) {
                    #pragma unroll
                    for (int hh = 0; hh < 2; hh++) {
                        float* d = acc[mt][np * 2 + hh];
                        mma_bf16(d, ah[mt], bh + hh * 2);
                        mma_bf16(d, ah[mt], bl + hh * 2);
                        mma_bf16(d, al[mt], bh + hh * 2);
                    }
                }
            }
        }
        __syncthreads();
    }

    // ---- epilogue: stage [o][p] in smem, then coalesced float4 stores
    const int lr  = lane >> 2;
    const int lc2 = (lane & 3) << 1;
    #pragma unroll
    for (int mt = 0; mt < 2; mt++) {
        int row0 = w * 32 + mt * 16 + lr;
        #pragma unroll
        for (int nt = 0; nt < 8; nt++) {
            int col = nt * 8 + lc2;
            stg[col * SPITCH + row0]           = acc[mt][nt][0];
            stg[(col + 1) * SPITCH + row0]     = acc[mt][nt][1];
            stg[col * SPITCH + row0 + 8]       = acc[mt][nt][2];
            stg[(col + 1) * SPITCH + row0 + 8] = acc[mt][nt][3];
        }
    }
    __syncthreads();
    for (int i = t; i < 2048; i += 128) {
        int o = i >> 5, q = i & 31;
        float4 v = *((const float4*)(stg + o * SPITCH + q * 4));
        *((float4*)(g_part + ((size_t)kh * COUT + o) * PTOT + pbase + pl0 + q * 4)) = v;
    }
}

// ---------------------------------------------------------------------------
// Combine K-split partials + bias, per-channel mean/var (deterministic).
// ---------------------------------------------------------------------------
__global__ __launch_bounds__(256) void stats_kernel(
    const float* __restrict__ bconv,
    const float* __restrict__ gamma, const float* __restrict__ beta)
{
    const int o = blockIdx.x;
    const int t = threadIdx.x;
    const float4* r0 = (const float4*)(g_part + ((size_t)0 * COUT + o) * PTOT);
    const float4* r1 = (const float4*)(g_part + ((size_t)1 * COUT + o) * PTOT);
    const float4* r2 = (const float4*)(g_part + ((size_t)2 * COUT + o) * PTOT);
    const float4* r3 = (const float4*)(g_part + ((size_t)3 * COUT + o) * PTOT);
    float4*       pr = (float4*)(g_pre + (size_t)o * PTOT);
    const float bb = bconv[o];

    float s = 0.f, s2 = 0.f;
    for (int i = t; i < PTOT / 4; i += 256) {
        float4 a = r0[i], b = r1[i], c = r2[i], d = r3[i];
        float4 v;
        v.x = a.x + b.x + c.x + d.x + bb;
        v.y = a.y + b.y + c.y + d.y + bb;
        v.z = a.z + b.z + c.z + d.z + bb;
        v.w = a.w + b.w + c.w + d.w + bb;
        pr[i] = v;
        s  += v.x + v.y + v.z + v.w;
        s2 += v.x * v.x + v.y * v.y + v.z * v.z + v.w * v.w;
    }
    __shared__ float rs[256], rs2[256];
    rs[t] = s; rs2[t] = s2;
    __syncthreads();
    for (int st = 128; st > 0; st >>= 1) {
        if (t < st) { rs[t] += rs[t + st]; rs2[t] += rs2[t + st]; }
        __syncthreads();
    }
    if (t == 0) {
        float mean = rs[0] * (1.0f / PTOT);
        float var  = rs2[0] * (1.0f / PTOT) - mean * mean;
        float inv  = rsqrtf(var + 1e-5f);
        float sc   = gamma[o] * inv;
        g_scale[o] = sc;
        g_shift[o] = beta[o] - mean * sc;
    }
}

// ---------------------------------------------------------------------------
__global__ __launch_bounds__(256) void norm_kernel(float* __restrict__ out)
{
    int e = blockIdx.x * 256 + threadIdx.x;
    if (e >= BS * COUT * NPTS / 4) return;
    int nq = e & (NPTS / 4 - 1);
    int o  = (e >> 11) & 63;
    int b  = e >> 17;
    float4 v = *((const float4*)(g_pre + (size_t)o * PTOT + (b << 13)) + nq);
    float sc = g_scale[o], sh = g_shift[o];
    float4 r = make_float4(v.x * sc + sh, v.y * sc + sh, v.z * sc + sh, v.w * sc + sh);
    *((float4*)out + e) = r;
}

// ---------------------------------------------------------------------------
extern "C" void kernel_launch(void* const* d_in, const int* in_sizes, int n_in,
                              void* d_out, int out_size)
{
    const float* x     = (const float*)d_in[0];
    const float* feat  = (const float*)d_in[1];
    const int*   neigh = (const int*)  d_in[2];
    const float* Bmat  = (const float*)d_in[3];
    const float* kern  = (const float*)d_in[4];
    const float* onep  = (const float*)d_in[5];
    const float* Wmlp  = (const float*)d_in[6];
    const float* bmlp  = (const float*)d_in[7];
    const float* Wconv = (const float*)d_in[8];
    const float* bconv = (const float*)d_in[9];
    const float* gamma = (const float*)d_in[10];
    const float* beta  = (const float*)d_in[11];
    float* out = (float*)d_out;

    cudaFuncSetAttribute(gemm_kernel, cudaFuncAttributeMaxDynamicSharedMemorySize, GEMM_SMEM);

    prep_w<<<(COUT * KCONV + 255) / 256, 256>>>(Wconv);
    transpose_f<<<(BS * CIN * NPTS + 255) / 256, 256>>>(feat);
    transpose_x<<<(BS * 3 * NPTS + 255) / 256, 256>>>(x);
    for (int c = 0; c < NCHUNK; c++) {
        point_kernel<<<CHUNK / PPB, 128>>>(c * CHUNK, neigh, Bmat, kern, onep, Wmlp, bmlp);
        gemm_kernel<<<dim3(CHUNK / 128, KSPLIT), 128, GEMM_SMEM>>>(c * CHUNK);
    }
    stats_kernel<<<COUT, 256>>>(bconv, gamma, beta);
    norm_kernel<<<(BS * COUT * NPTS / 4 + 255) / 256, 256>>>(out);
}

// round 11
// speedup vs baseline: 1.5685x; 1.1453x over previous
#include <cuda_runtime.h>
#include <cuda_bf16.h>
#include <math.h>
#include <stdint.h>

#define BS     4
#define NPTS   8192
#define KNB    32
#define CIN    64
#define CX     32
#define CF     96
#define COUT   64
#define KCONV  3072
#define PTOT   32768
#define CHUNK  8192
#define NCHUNK (PTOT / CHUNK)
#define KSPLIT 4
#define KPART  (KCONV / KSPLIT)   // 768
#define PPB    8                  // points per block in point_kernel

// ---- device scratch (allocation-free: static __device__ globals) ----
__device__ float g_ft[BS * NPTS * CIN];                  // feature point-major (8 MB)
__device__ float g_xt[BS * NPTS * 4];                    // coords point-major (512 KB)
__device__ float g_G[(size_t)CHUNK * KCONV];             // per-chunk flat feats (100 MB)
__device__ float g_part[(size_t)KSPLIT * COUT * PTOT];   // K-split partials (32 MB)
__device__ float g_pre[(size_t)COUT * PTOT];             // combined pre-BN (8 MB)
__device__ float g_scale[COUT];
__device__ float g_shift[COUT];
__device__ __nv_bfloat16 g_Whi[(size_t)COUT * KCONV];    // W split hi (384 KB)
__device__ __nv_bfloat16 g_Wlo[(size_t)COUT * KCONV];    // W split lo (384 KB)

// ===========================================================================
// PTX helpers: ldmatrix + warp-level bf16 mma (PTX ISA 7.x, valid on compute_100)
// ===========================================================================
__device__ __forceinline__ uint32_t smem_u32(const void* p) {
    uint32_t a;
    asm("{ .reg .u64 t; cvta.to.shared.u64 t, %1; cvt.u32.u64 %0, t; }" : "=r"(a) : "l"(p));
    return a;
}
__device__ __forceinline__ void ldsm4(uint32_t* r, uint32_t addr) {
    asm volatile("ldmatrix.sync.aligned.m8n8.x4.shared.b16 {%0,%1,%2,%3}, [%4];"
                 : "=r"(r[0]), "=r"(r[1]), "=r"(r[2]), "=r"(r[3]) : "r"(addr));
}
__device__ __forceinline__ void mma_bf16(float* d, const uint32_t* a, const uint32_t* b) {
    asm volatile(
        "mma.sync.aligned.m16n8k16.row.col.f32.bf16.bf16.f32 "
        "{%0,%1,%2,%3}, {%4,%5,%6,%7}, {%8,%9}, {%0,%1,%2,%3};"
        : "+f"(d[0]), "+f"(d[1]), "+f"(d[2]), "+f"(d[3])
        : "r"(a[0]), "r"(a[1]), "r"(a[2]), "r"(a[3]), "r"(b[0]), "r"(b[1]));
}
__device__ __forceinline__ uint32_t bfpack(float a, float b) {
    __nv_bfloat16 ha = __float2bfloat16_rn(a), hb = __float2bfloat16_rn(b);
    return ((uint32_t)__bfloat16_as_ushort(hb) << 16) | (uint32_t)__bfloat16_as_ushort(ha);
}

// ---------------------------------------------------------------------------
__global__ __launch_bounds__(256) void prep_w(const float* __restrict__ Wconv)
{
    int e = blockIdx.x * 256 + threadIdx.x;          // COUT*KCONV = 196608
    if (e >= COUT * KCONV) return;
    float w = Wconv[e];
    __nv_bfloat16 hi = __float2bfloat16_rn(w);
    g_Whi[e] = hi;
    g_Wlo[e] = __float2bfloat16_rn(w - __bfloat162float(hi));
}

// ---------------------------------------------------------------------------
__global__ __launch_bounds__(256) void transpose_f(const float* __restrict__ f)
{
    int e = blockIdx.x * 256 + threadIdx.x;
    if (e >= BS * CIN * NPTS) return;
    int n = e & (NPTS - 1);
    int c = (e >> 13) & 63;
    int b = e >> 19;
    g_ft[(((size_t)(b << 13) + n) << 6) + c] = f[e];
}

__global__ __launch_bounds__(256) void transpose_x(const float* __restrict__ x)
{
    int e = blockIdx.x * 256 + threadIdx.x;
    if (e >= BS * 3 * NPTS) return;
    int b = e / (3 * NPTS);
    int r = e - b * 3 * NPTS;
    int d = r >> 13;
    int n = r & (NPTS - 1);
    g_xt[(((b << 13) + n) << 2) + d] = x[e];
}

// ---------------------------------------------------------------------------
// Per-point kernel, restructured (R9 theory) + alignment fix:
//  - all phases use all 128 threads (k = lane, per-warp m/j/o octets)
//  - 3 barriers per point
//  - depth-1 register prefetch of next point's gathers under the contraction
//  - s_pe read SCALAR only (65-float pitch is not 16B-aligned per row)
//  - float4-accessed shared arrays carry __align__(16)
// ---------------------------------------------------------------------------
__global__ __launch_bounds__(128, 4) void point_kernel(
    int          pbase,
    const int*   __restrict__ neigh,
    const float* __restrict__ Bmat,
    const float* __restrict__ kern,
    const float* __restrict__ one_pad,
    const float* __restrict__ Wmlp,
    const float* __restrict__ bmlp)
{
    const int t    = threadIdx.x;
    const int lane = t & 31;
    const int w    = t >> 5;

    __shared__ float s_pe[32][65];                  // [k][f] scalar access only
    __shared__ __align__(16) float s_xf[32][36];    // x_feats [k][o], 144B rows
    __shared__ float s_perm[32][33];                // [k][j] raw
    __shared__ float s_op[32][33];                  // one_padding
    __shared__ __align__(16) float s_f[32][64];     // gathered features [k][c]
    __shared__ float s_W[32][64];                   // W_mlp [o][f]
    __shared__ float s_B[7][32];
    __shared__ float s_k[3][32];
    __shared__ float s_bm[32];

    for (int i = t; i < 224;  i += 128) s_B[i >> 5][i & 31]  = Bmat[i];
    for (int i = t; i < 96;   i += 128) s_k[i >> 5][i & 31]  = kern[i];
    for (int i = t; i < 2048; i += 128) s_W[i >> 6][i & 63]  = Wmlp[i];
    for (int i = t; i < 1024; i += 128) s_op[i >> 5][i & 31] = one_pad[i];
    if (t < 32) s_bm[t] = bmlp[t];

    const int   b      = pbase >> 13;                    // batch index (constant)
    const float* ftb   = g_ft + ((size_t)b << 19);       // batch feature base
    const float* xtb   = g_xt + ((size_t)b << 15);       // batch coord base
    const int   p0     = pbase + blockIdx.x * PPB;

    const int kr = t >> 4;          // gather row base (0..7)
    const int c4 = t & 15;          // gather quad

    // ---- prefetch registers for the current point
    float4 fv[4];
    float4 xnl, xn0;

    {   // initial prefetch (ip = 0)
        const int pb5 = (p0 - pbase) << 5;
        int i0 = neigh[pb5];
        int il = neigh[pb5 + lane];
        xn0 = *((const float4*)(xtb + ((size_t)i0 << 2)));
        xnl = *((const float4*)(xtb + ((size_t)il << 2)));
        #pragma unroll
        for (int r = 0; r < 4; r++) {
            int idx = neigh[pb5 + kr + r * 8];
            fv[r] = *((const float4*)(ftb + ((size_t)idx << 6) + (c4 << 2)));
        }
    }
    __syncthreads();   // constants ready

    const float TWO_PI = 6.283185307179586f;

    for (int ip = 0; ip < PPB; ip++) {
        const int pl = blockIdx.x * PPB + ip;            // chunk-local point

        // ---- store phase: commit prefetched gathers to smem
        #pragma unroll
        for (int r = 0; r < 4; r++)
            *((float4*)&s_f[kr + r * 8][c4 << 2]) = fv[r];

        // rel/dis per lane (k = lane), in registers
        const float r0 = xnl.x - xn0.x;
        const float r1 = xnl.y - xn0.y;
        const float r2 = xnl.z - xn0.z;
        const float dis = sqrtf(fmaxf(r0 * r0 + r1 * r1 + r2 * r2, 1e-12f));

        // pe: k = lane, m in [w*8, w*8+8)
        #pragma unroll
        for (int i = 0; i < 8; i++) {
            const int m = (w << 3) + i;
            float acc = xn0.x * s_B[0][m] + xn0.y * s_B[1][m] + xn0.z * s_B[2][m]
                      + r0 * s_B[3][m] + r1 * s_B[4][m] + r2 * s_B[5][m]
                      + dis * s_B[6][m];
            acc *= TWO_PI;
            float sv, cv;
            __sincosf(acc, &sv, &cv);
            s_pe[lane][m]      = sv;
            s_pe[lane][32 + m] = cv;
        }
        // perm raw: k = lane, j in [w*8, w*8+8)
        #pragma unroll
        for (int i = 0; i < 8; i++) {
            const int j = (w << 3) + i;
            float v = s_op[lane][j] + r0 * s_k[0][j] + r1 * s_k[1][j] + r2 * s_k[2][j];
            s_perm[lane][j] = fmaxf(v, 0.0f);
        }
        __syncthreads();   // A: s_f, s_pe, s_perm ready

        // ---- MLP: k = lane, outputs o in [w*8, w*8+8)  (SCALAR s_pe reads)
        {
            const int o0 = w << 3;
            float acc[8];
            #pragma unroll
            for (int i = 0; i < 8; i++) acc[i] = s_bm[o0 + i];
            #pragma unroll
            for (int f = 0; f < 64; f++) {
                float pv = s_pe[lane][f];
                #pragma unroll
                for (int i = 0; i < 8; i++) acc[i] += pv * s_W[o0 + i][f];
            }
            *((float4*)&s_xf[lane][o0])     = make_float4(acc[0], acc[1], acc[2], acc[3]);
            *((float4*)&s_xf[lane][o0 + 4]) = make_float4(acc[4], acc[5], acc[6], acc[7]);
        }

        // ---- pr load + fused column-normalization (thread owns column j = lane)
        float pr[32];
        float sum = 0.f;
        #pragma unroll
        for (int k = 0; k < 32; k++) { pr[k] = s_perm[k][lane]; sum += pr[k]; }
        const float inv = 1.0f / (sum + 1e-6f);
        #pragma unroll
        for (int k = 0; k < 32; k++) pr[k] *= inv;

        // ---- prefetch next point's gathers (hidden under contraction)
        if (ip + 1 < PPB) {
            const int pb5 = (pl + 1) << 5;
            int i0 = neigh[pb5];
            int il = neigh[pb5 + lane];
            xn0 = *((const float4*)(xtb + ((size_t)i0 << 2)));
            xnl = *((const float4*)(xtb + ((size_t)il << 2)));
            #pragma unroll
            for (int r = 0; r < 4; r++) {
                int idx = neigh[pb5 + kr + r * 8];
                fv[r] = *((const float4*)(ftb + ((size_t)idx << 6) + (c4 << 2)));
            }
        }
        __syncthreads();   // B: s_xf ready

        // ---- contraction: G[c][j] = sum_k feats[c][k] * perm[k][j]
        float* gp = g_G + (size_t)pl * KCONV + lane;
        #pragma unroll
        for (int q = 0; q < 6; q++) {
            const int c0 = (q * 4 + w) * 4;    // uniform per warp, 0..92
            float a0 = 0.f, a1 = 0.f, a2 = 0.f, a3 = 0.f;
            if (c0 < 64) {
                #pragma unroll
                for (int k = 0; k < 32; k++) {
                    float4 f = *((const float4*)&s_f[k][c0]);
                    a0 += f.x * pr[k]; a1 += f.y * pr[k];
                    a2 += f.z * pr[k]; a3 += f.w * pr[k];
                }
            } else {
                #pragma unroll
                for (int k = 0; k < 32; k++) {
                    float4 f = *((const float4*)&s_xf[k][c0 - 64]);
                    a0 += f.x * pr[k]; a1 += f.y * pr[k];
                    a2 += f.z * pr[k]; a3 += f.w * pr[k];
                }
            }
            gp[(size_t)(c0 + 0) * 32] = a0;
            gp[(size_t)(c0 + 1) * 32] = a1;
            gp[(size_t)(c0 + 2) * 32] = a2;
            gp[(size_t)(c0 + 3) * 32] = a3;
        }
        __syncthreads();   // C: contraction reads done before next STS
    }
}

// ---------------------------------------------------------------------------
// bf16 3-term split GEMM via warp-level mma.sync (HMMA) — unchanged from R8.
// ---------------------------------------------------------------------------
#define OFF_AHI 0
#define OFF_ALO 18432
#define OFF_WHI 36864
#define OFF_WLO 46080
#define GEMM_SMEM 55296
#define APITCH 72
#define SPITCH 132

__global__ __launch_bounds__(128) void gemm_kernel(int pbase)
{
    extern __shared__ char smem[];
    __nv_bfloat16* Ahi = (__nv_bfloat16*)(smem + OFF_AHI);
    __nv_bfloat16* Alo = (__nv_bfloat16*)(smem + OFF_ALO);
    __nv_bfloat16* Whs = (__nv_bfloat16*)(smem + OFF_WHI);
    __nv_bfloat16* Wls = (__nv_bfloat16*)(smem + OFF_WLO);
    float*         stg = (float*)smem;
    const uint32_t sb  = smem_u32(smem);

    const int t    = threadIdx.x;
    const int lane = t & 31;
    const int w    = t >> 5;
    const int pl0  = blockIdx.x * 128;
    const int kh   = blockIdx.y;
    const int kb   = kh * KPART;

    float acc[2][8][4];
    #pragma unroll
    for (int mt = 0; mt < 2; mt++)
        #pragma unroll
        for (int nt = 0; nt < 8; nt++)
            #pragma unroll
            for (int i = 0; i < 4; i++) acc[mt][nt][i] = 0.f;

    const int wrow  = t >> 1;
    const int whalf = t & 1;

    const int a_row  = (lane & 15);
    const int a_col  = (lane >> 4) << 3;
    const int b_n    = (lane & 7) + (((lane >> 4) & 1) << 3);
    const int b_koff = ((lane >> 3) & 1) << 3;

    for (int kc = 0; kc < KPART / 64; kc++) {
        {
            const float* src = g_G + (size_t)(pl0 + t) * KCONV + kb + kc * 64;
            #pragma unroll
            for (int j = 0; j < 8; j++) {
                float4 f0 = *((const float4*)(src + j * 8));
                float4 f1 = *((const float4*)(src + j * 8 + 4));
                float v[8] = {f0.x, f0.y, f0.z, f0.w, f1.x, f1.y, f1.z, f1.w};
                float r[8];
                #pragma unroll
                for (int i = 0; i < 8; i++) {
                    __nv_bfloat16 hb = __float2bfloat16_rn(v[i]);
                    r[i] = v[i] - __bfloat162float(hb);
                }
                uint4 hv, lv;
                hv.x = bfpack(v[0], v[1]); hv.y = bfpack(v[2], v[3]);
                hv.z = bfpack(v[4], v[5]); hv.w = bfpack(v[6], v[7]);
                lv.x = bfpack(r[0], r[1]); lv.y = bfpack(r[2], r[3]);
                lv.z = bfpack(r[4], r[5]); lv.w = bfpack(r[6], r[7]);
                *((uint4*)(Ahi + t * APITCH + j * 8)) = hv;
                *((uint4*)(Alo + t * APITCH + j * 8)) = lv;
            }
        }
        {
            size_t off = (size_t)wrow * KCONV + kb + kc * 64 + whalf * 32;
            const uint4* wh = (const uint4*)(g_Whi + off);
            const uint4* wl = (const uint4*)(g_Wlo + off);
            #pragma unroll
            for (int i = 0; i < 4; i++) {
                *((uint4*)(Whs + wrow * APITCH + whalf * 32 + i * 8)) = wh[i];
                *((uint4*)(Wls + wrow * APITCH + whalf * 32 + i * 8)) = wl[i];
            }
        }
        __syncthreads();

        #pragma unroll
        for (int s = 0; s < 4; s++) {
            const int k0 = s * 16;
            uint32_t ah[2][4], al[2][4];
            #pragma unroll
            for (int mt = 0; mt < 2; mt++) {
                int row = w * 32 + mt * 16 + a_row;
                uint32_t addr = sb + OFF_AHI + (uint32_t)(row * APITCH + a_col + k0) * 2;
                ldsm4(ah[mt], addr);
                addr = sb + OFF_ALO + (uint32_t)(row * APITCH + a_col + k0) * 2;
                ldsm4(al[mt], addr);
            }
            #pragma unroll
            for (int np = 0; np < 4; np++) {
                int n = np * 16 + b_n;
                uint32_t bh[4], bl[4];
                uint32_t addr = sb + OFF_WHI + (uint32_t)(n * APITCH + k0 + b_koff) * 2;
                ldsm4(bh, addr);
                addr = sb + OFF_WLO + (uint32_t)(n * APITCH + k0 + b_koff) * 2;
                ldsm4(bl, addr);
                #pragma unroll
                for (int mt = 0; mt < 2; mt++) {
                    #pragma unroll
                    for (int hh = 0; hh < 2; hh++) {
                        float* d = acc[mt][np * 2 + hh];
                        mma_bf16(d, ah[mt], bh + hh * 2);
                        mma_bf16(d, ah[mt], bl + hh * 2);
                        mma_bf16(d, al[mt], bh + hh * 2);
                    }
                }
            }
        }
        __syncthreads();
    }

    const int lr  = lane >> 2;
    const int lc2 = (lane & 3) << 1;
    #pragma unroll
    for (int mt = 0; mt < 2; mt++) {
        int row0 = w * 32 + mt * 16 + lr;
        #pragma unroll
        for (int nt = 0; nt < 8; nt++) {
            int col = nt * 8 + lc2;
            stg[col * SPITCH + row0]           = acc[mt][nt][0];
            stg[(col + 1) * SPITCH + row0]     = acc[mt][nt][1];
            stg[col * SPITCH + row0 + 8]       = acc[mt][nt][2];
            stg[(col + 1) * SPITCH + row0 + 8] = acc[mt][nt][3];
        }
    }
    __syncthreads();
    for (int i = t; i < 2048; i += 128) {
        int o = i >> 5, q = i & 31;
        float4 v = *((const float4*)(stg + o * SPITCH + q * 4));
        *((float4*)(g_part + ((size_t)kh * COUT + o) * PTOT + pbase + pl0 + q * 4)) = v;
    }
}

// ---------------------------------------------------------------------------
__global__ __launch_bounds__(256) void stats_kernel(
    const float* __restrict__ bconv,
    const float* __restrict__ gamma, const float* __restrict__ beta)
{
    const int o = blockIdx.x;
    const int t = threadIdx.x;
    const float4* r0 = (const float4*)(g_part + ((size_t)0 * COUT + o) * PTOT);
    const float4* r1 = (const float4*)(g_part + ((size_t)1 * COUT + o) * PTOT);
    const float4* r2 = (const float4*)(g_part + ((size_t)2 * COUT + o) * PTOT);
    const float4* r3 = (const float4*)(g_part + ((size_t)3 * COUT + o) * PTOT);
    float4*       pr = (float4*)(g_pre + (size_t)o * PTOT);
    const float bb = bconv[o];

    float s = 0.f, s2 = 0.f;
    for (int i = t; i < PTOT / 4; i += 256) {
        float4 a = r0[i], b = r1[i], c = r2[i], d = r3[i];
        float4 v;
        v.x = a.x + b.x + c.x + d.x + bb;
        v.y = a.y + b.y + c.y + d.y + bb;
        v.z = a.z + b.z + c.z + d.z + bb;
        v.w = a.w + b.w + c.w + d.w + bb;
        pr[i] = v;
        s  += v.x + v.y + v.z + v.w;
        s2 += v.x * v.x + v.y * v.y + v.z * v.z + v.w * v.w;
    }
    __shared__ float rs[256], rs2[256];
    rs[t] = s; rs2[t] = s2;
    __syncthreads();
    for (int st = 128; st > 0; st >>= 1) {
        if (t < st) { rs[t] += rs[t + st]; rs2[t] += rs2[t + st]; }
        __syncthreads();
    }
    if (t == 0) {
        float mean = rs[0] * (1.0f / PTOT);
        float var  = rs2[0] * (1.0f / PTOT) - mean * mean;
        float inv  = rsqrtf(var + 1e-5f);
        float sc   = gamma[o] * inv;
        g_scale[o] = sc;
        g_shift[o] = beta[o] - mean * sc;
    }
}

// ---------------------------------------------------------------------------
__global__ __launch_bounds__(256) void norm_kernel(float* __restrict__ out)
{
    int e = blockIdx.x * 256 + threadIdx.x;
    if (e >= BS * COUT * NPTS / 4) return;
    int nq = e & (NPTS / 4 - 1);
    int o  = (e >> 11) & 63;
    int b  = e >> 17;
    float4 v = *((const float4*)(g_pre + (size_t)o * PTOT + (b << 13)) + nq);
    float sc = g_scale[o], sh = g_shift[o];
    float4 r = make_float4(v.x * sc + sh, v.y * sc + sh, v.z * sc + sh, v.w * sc + sh);
    *((float4*)out + e) = r;
}

// ---------------------------------------------------------------------------
extern "C" void kernel_launch(void* const* d_in, const int* in_sizes, int n_in,
                              void* d_out, int out_size)
{
    const float* x     = (const float*)d_in[0];
    const float* feat  = (const float*)d_in[1];
    const int*   neigh = (const int*)  d_in[2];
    const float* Bmat  = (const float*)d_in[3];
    const float* kern  = (const float*)d_in[4];
    const float* onep  = (const float*)d_in[5];
    const float* Wmlp  = (const float*)d_in[6];
    const float* bmlp  = (const float*)d_in[7];
    const float* Wconv = (const float*)d_in[8];
    const float* bconv = (const float*)d_in[9];
    const float* gamma = (const float*)d_in[10];
    const float* beta  = (const float*)d_in[11];
    float* out = (float*)d_out;

    cudaFuncSetAttribute(gemm_kernel, cudaFuncAttributeMaxDynamicSharedMemorySize, GEMM_SMEM);

    prep_w<<<(COUT * KCONV + 255) / 256, 256>>>(Wconv);
    transpose_f<<<(BS * CIN * NPTS + 255) / 256, 256>>>(feat);
    transpose_x<<<(BS * 3 * NPTS + 255) / 256, 256>>>(x);
    for (int c = 0; c < NCHUNK; c++) {
        // neigh is indexed per-batch inside point_kernel via (pl+..)<<5 offsets
        point_kernel<<<CHUNK / PPB, 128>>>(c * CHUNK, neigh + (size_t)c * CHUNK * KNB,
                                           Bmat, kern, onep, Wmlp, bmlp);
        gemm_kernel<<<dim3(CHUNK / 128, KSPLIT), 128, GEMM_SMEM>>>(c * CHUNK);
    }
    stats_kernel<<<COUT, 256>>>(bconv, gamma, beta);
    norm_kernel<<<(BS * COUT * NPTS / 4 + 255) / 256, 256>>>(out);
}

// round 12
// speedup vs baseline: 1.5694x; 1.0006x over previous
#include <cuda_runtime.h>
#include <cuda_bf16.h>
#include <math.h>
#include <stdint.h>

#define BS     4
#define NPTS   8192
#define KNB    32
#define CIN    64
#define CX     32
#define CF     96
#define COUT   64
#define KCONV  3072
#define PTOT   32768
#define CHUNK  8192
#define NCHUNK (PTOT / CHUNK)
#define KSPLIT 4
#define KPART  (KCONV / KSPLIT)   // 768
#define PPB    8                  // points per block in point_kernel

// ---- device scratch (allocation-free: static __device__ globals) ----
__device__ float g_ft[BS * NPTS * CIN];                  // feature point-major (8 MB)
__device__ float g_xt[BS * NPTS * 4];                    // coords point-major (512 KB)
__device__ float g_G[(size_t)CHUNK * KCONV];             // per-chunk flat feats (100 MB)
__device__ float g_part[(size_t)KSPLIT * COUT * PTOT];   // K-split partials (32 MB)
__device__ float g_pre[(size_t)COUT * PTOT];             // combined pre-BN (8 MB)
__device__ float g_scale[COUT];
__device__ float g_shift[COUT];
__device__ __nv_bfloat16 g_Whi[(size_t)COUT * KCONV];    // W split hi (384 KB)
__device__ __nv_bfloat16 g_Wlo[(size_t)COUT * KCONV];    // W split lo (384 KB)

// ===========================================================================
// PTX helpers: ldmatrix + warp-level bf16 mma (PTX ISA 7.x, valid on compute_100)
// ===========================================================================
__device__ __forceinline__ uint32_t smem_u32(const void* p) {
    uint32_t a;
    asm("{ .reg .u64 t; cvta.to.shared.u64 t, %1; cvt.u32.u64 %0, t; }" : "=r"(a) : "l"(p));
    return a;
}
__device__ __forceinline__ void ldsm4(uint32_t* r, uint32_t addr) {
    asm volatile("ldmatrix.sync.aligned.m8n8.x4.shared.b16 {%0,%1,%2,%3}, [%4];"
                 : "=r"(r[0]), "=r"(r[1]), "=r"(r[2]), "=r"(r[3]) : "r"(addr));
}
__device__ __forceinline__ void mma_bf16(float* d, const uint32_t* a, const uint32_t* b) {
    asm volatile(
        "mma.sync.aligned.m16n8k16.row.col.f32.bf16.bf16.f32 "
        "{%0,%1,%2,%3}, {%4,%5,%6,%7}, {%8,%9}, {%0,%1,%2,%3};"
        : "+f"(d[0]), "+f"(d[1]), "+f"(d[2]), "+f"(d[3])
        : "r"(a[0]), "r"(a[1]), "r"(a[2]), "r"(a[3]), "r"(b[0]), "r"(b[1]));
}
__device__ __forceinline__ uint32_t bfpack(float a, float b) {
    __nv_bfloat16 ha = __float2bfloat16_rn(a), hb = __float2bfloat16_rn(b);
    return ((uint32_t)__bfloat16_as_ushort(hb) << 16) | (uint32_t)__bfloat16_as_ushort(ha);
}

// ---------------------------------------------------------------------------
__global__ __launch_bounds__(256) void prep_w(const float* __restrict__ Wconv)
{
    int e = blockIdx.x * 256 + threadIdx.x;          // COUT*KCONV = 196608
    if (e >= COUT * KCONV) return;
    float w = Wconv[e];
    __nv_bfloat16 hi = __float2bfloat16_rn(w);
    g_Whi[e] = hi;
    g_Wlo[e] = __float2bfloat16_rn(w - __bfloat162float(hi));
}

// ---------------------------------------------------------------------------
__global__ __launch_bounds__(256) void transpose_f(const float* __restrict__ f)
{
    int e = blockIdx.x * 256 + threadIdx.x;
    if (e >= BS * CIN * NPTS) return;
    int n = e & (NPTS - 1);
    int c = (e >> 13) & 63;
    int b = e >> 19;
    g_ft[(((size_t)(b << 13) + n) << 6) + c] = f[e];
}

__global__ __launch_bounds__(256) void transpose_x(const float* __restrict__ x)
{
    int e = blockIdx.x * 256 + threadIdx.x;
    if (e >= BS * 3 * NPTS) return;
    int b = e / (3 * NPTS);
    int r = e - b * 3 * NPTS;
    int d = r >> 13;
    int n = r & (NPTS - 1);
    g_xt[(((b << 13) + n) << 2) + d] = x[e];
}

// ---------------------------------------------------------------------------
// Per-point kernel, restructured (R9 theory) + alignment fix:
//  - all phases use all 128 threads (k = lane, per-warp m/j/o octets)
//  - 3 barriers per point
//  - depth-1 register prefetch of next point's gathers under the contraction
//  - s_pe read SCALAR only (65-float pitch is not 16B-aligned per row)
//  - float4-accessed shared arrays carry __align__(16)
// ---------------------------------------------------------------------------
__global__ __launch_bounds__(128, 4) void point_kernel(
    int          pbase,
    const int*   __restrict__ neigh,
    const float* __restrict__ Bmat,
    const float* __restrict__ kern,
    const float* __restrict__ one_pad,
    const float* __restrict__ Wmlp,
    const float* __restrict__ bmlp)
{
    const int t    = threadIdx.x;
    const int lane = t & 31;
    const int w    = t >> 5;

    __shared__ float s_pe[32][65];                  // [k][f] scalar access only
    __shared__ __align__(16) float s_xf[32][36];    // x_feats [k][o], 144B rows
    __shared__ float s_perm[32][33];                // [k][j] raw
    __shared__ float s_op[32][33];                  // one_padding
    __shared__ __align__(16) float s_f[32][64];     // gathered features [k][c]
    __shared__ float s_W[32][64];                   // W_mlp [o][f]
    __shared__ float s_B[7][32];
    __shared__ float s_k[3][32];
    __shared__ float s_bm[32];

    for (int i = t; i < 224;  i += 128) s_B[i >> 5][i & 31]  = Bmat[i];
    for (int i = t; i < 96;   i += 128) s_k[i >> 5][i & 31]  = kern[i];
    for (int i = t; i < 2048; i += 128) s_W[i >> 6][i & 63]  = Wmlp[i];
    for (int i = t; i < 1024; i += 128) s_op[i >> 5][i & 31] = one_pad[i];
    if (t < 32) s_bm[t] = bmlp[t];

    const int   b      = pbase >> 13;                    // batch index (constant)
    const float* ftb   = g_ft + ((size_t)b << 19);       // batch feature base
    const float* xtb   = g_xt + ((size_t)b << 15);       // batch coord base
    const int   p0     = pbase + blockIdx.x * PPB;

    const int kr = t >> 4;          // gather row base (0..7)
    const int c4 = t & 15;          // gather quad

    // ---- prefetch registers for the current point
    float4 fv[4];
    float4 xnl, xn0;

    {   // initial prefetch (ip = 0)
        const int pb5 = (p0 - pbase) << 5;
        int i0 = neigh[pb5];
        int il = neigh[pb5 + lane];
        xn0 = *((const float4*)(xtb + ((size_t)i0 << 2)));
        xnl = *((const float4*)(xtb + ((size_t)il << 2)));
        #pragma unroll
        for (int r = 0; r < 4; r++) {
            int idx = neigh[pb5 + kr + r * 8];
            fv[r] = *((const float4*)(ftb + ((size_t)idx << 6) + (c4 << 2)));
        }
    }
    __syncthreads();   // constants ready

    const float TWO_PI = 6.283185307179586f;

    for (int ip = 0; ip < PPB; ip++) {
        const int pl = blockIdx.x * PPB + ip;            // chunk-local point

        // ---- store phase: commit prefetched gathers to smem
        #pragma unroll
        for (int r = 0; r < 4; r++)
            *((float4*)&s_f[kr + r * 8][c4 << 2]) = fv[r];

        // rel/dis per lane (k = lane), in registers
        const float r0 = xnl.x - xn0.x;
        const float r1 = xnl.y - xn0.y;
        const float r2 = xnl.z - xn0.z;
        const float dis = sqrtf(fmaxf(r0 * r0 + r1 * r1 + r2 * r2, 1e-12f));

        // pe: k = lane, m in [w*8, w*8+8)
        #pragma unroll
        for (int i = 0; i < 8; i++) {
            const int m = (w << 3) + i;
            float acc = xn0.x * s_B[0][m] + xn0.y * s_B[1][m] + xn0.z * s_B[2][m]
                      + r0 * s_B[3][m] + r1 * s_B[4][m] + r2 * s_B[5][m]
                      + dis * s_B[6][m];
            acc *= TWO_PI;
            float sv, cv;
            __sincosf(acc, &sv, &cv);
            s_pe[lane][m]      = sv;
            s_pe[lane][32 + m] = cv;
        }
        // perm raw: k = lane, j in [w*8, w*8+8)
        #pragma unroll
        for (int i = 0; i < 8; i++) {
            const int j = (w << 3) + i;
            float v = s_op[lane][j] + r0 * s_k[0][j] + r1 * s_k[1][j] + r2 * s_k[2][j];
            s_perm[lane][j] = fmaxf(v, 0.0f);
        }
        __syncthreads();   // A: s_f, s_pe, s_perm ready

        // ---- MLP: k = lane, outputs o in [w*8, w*8+8)  (SCALAR s_pe reads)
        {
            const int o0 = w << 3;
            float acc[8];
            #pragma unroll
            for (int i = 0; i < 8; i++) acc[i] = s_bm[o0 + i];
            #pragma unroll
            for (int f = 0; f < 64; f++) {
                float pv = s_pe[lane][f];
                #pragma unroll
                for (int i = 0; i < 8; i++) acc[i] += pv * s_W[o0 + i][f];
            }
            *((float4*)&s_xf[lane][o0])     = make_float4(acc[0], acc[1], acc[2], acc[3]);
            *((float4*)&s_xf[lane][o0 + 4]) = make_float4(acc[4], acc[5], acc[6], acc[7]);
        }

        // ---- pr load + fused column-normalization (thread owns column j = lane)
        float pr[32];
        float sum = 0.f;
        #pragma unroll
        for (int k = 0; k < 32; k++) { pr[k] = s_perm[k][lane]; sum += pr[k]; }
        const float inv = 1.0f / (sum + 1e-6f);
        #pragma unroll
        for (int k = 0; k < 32; k++) pr[k] *= inv;

        // ---- prefetch next point's gathers (hidden under contraction)
        if (ip + 1 < PPB) {
            const int pb5 = (pl + 1) << 5;
            int i0 = neigh[pb5];
            int il = neigh[pb5 + lane];
            xn0 = *((const float4*)(xtb + ((size_t)i0 << 2)));
            xnl = *((const float4*)(xtb + ((size_t)il << 2)));
            #pragma unroll
            for (int r = 0; r < 4; r++) {
                int idx = neigh[pb5 + kr + r * 8];
                fv[r] = *((const float4*)(ftb + ((size_t)idx << 6) + (c4 << 2)));
            }
        }
        __syncthreads();   // B: s_xf ready

        // ---- contraction: G[c][j] = sum_k feats[c][k] * perm[k][j]
        float* gp = g_G + (size_t)pl * KCONV + lane;
        #pragma unroll
        for (int q = 0; q < 6; q++) {
            const int c0 = (q * 4 + w) * 4;    // uniform per warp, 0..92
            float a0 = 0.f, a1 = 0.f, a2 = 0.f, a3 = 0.f;
            if (c0 < 64) {
                #pragma unroll
                for (int k = 0; k < 32; k++) {
                    float4 f = *((const float4*)&s_f[k][c0]);
                    a0 += f.x * pr[k]; a1 += f.y * pr[k];
                    a2 += f.z * pr[k]; a3 += f.w * pr[k];
                }
            } else {
                #pragma unroll
                for (int k = 0; k < 32; k++) {
                    float4 f = *((const float4*)&s_xf[k][c0 - 64]);
                    a0 += f.x * pr[k]; a1 += f.y * pr[k];
                    a2 += f.z * pr[k]; a3 += f.w * pr[k];
                }
            }
            gp[(size_t)(c0 + 0) * 32] = a0;
            gp[(size_t)(c0 + 1) * 32] = a1;
            gp[(size_t)(c0 + 2) * 32] = a2;
            gp[(size_t)(c0 + 3) * 32] = a3;
        }
        __syncthreads();   // C: contraction reads done before next STS
    }
}

// ---------------------------------------------------------------------------
// bf16 3-term split GEMM via warp-level mma.sync (HMMA) — unchanged from R8.
// ---------------------------------------------------------------------------
#define OFF_AHI 0
#define OFF_ALO 18432
#define OFF_WHI 36864
#define OFF_WLO 46080
#define GEMM_SMEM 55296
#define APITCH 72
#define SPITCH 132

__global__ __launch_bounds__(128) void gemm_kernel(int pbase)
{
    extern __shared__ char smem[];
    __nv_bfloat16* Ahi = (__nv_bfloat16*)(smem + OFF_AHI);
    __nv_bfloat16* Alo = (__nv_bfloat16*)(smem + OFF_ALO);
    __nv_bfloat16* Whs = (__nv_bfloat16*)(smem + OFF_WHI);
    __nv_bfloat16* Wls = (__nv_bfloat16*)(smem + OFF_WLO);
    float*         stg = (float*)smem;
    const uint32_t sb  = smem_u32(smem);

    const int t    = threadIdx.x;
    const int lane = t & 31;
    const int w    = t >> 5;
    const int pl0  = blockIdx.x * 128;
    const int kh   = blockIdx.y;
    const int kb   = kh * KPART;

    float acc[2][8][4];
    #pragma unroll
    for (int mt = 0; mt < 2; mt++)
        #pragma unroll
        for (int nt = 0; nt < 8; nt++)
            #pragma unroll
            for (int i = 0; i < 4; i++) acc[mt][nt][i] = 0.f;

    const int wrow  = t >> 1;
    const int whalf = t & 1;

    const int a_row  = (lane & 15);
    const int a_col  = (lane >> 4) << 3;
    const int b_n    = (lane & 7) + (((lane >> 4) & 1) << 3);
    const int b_koff = ((lane >> 3) & 1) << 3;

    for (int kc = 0; kc < KPART / 64; kc++) {
        {
            const float* src = g_G + (size_t)(pl0 + t) * KCONV + kb + kc * 64;
            #pragma unroll
            for (int j = 0; j < 8; j++) {
                float4 f0 = *((const float4*)(src + j * 8));
                float4 f1 = *((const float4*)(src + j * 8 + 4));
                float v[8] = {f0.x, f0.y, f0.z, f0.w, f1.x, f1.y, f1.z, f1.w};
                float r[8];
                #pragma unroll
                for (int i = 0; i < 8; i++) {
                    __nv_bfloat16 hb = __float2bfloat16_rn(v[i]);
                    r[i] = v[i] - __bfloat162float(hb);
                }
                uint4 hv, lv;
                hv.x = bfpack(v[0], v[1]); hv.y = bfpack(v[2], v[3]);
                hv.z = bfpack(v[4], v[5]); hv.w = bfpack(v[6], v[7]);
                lv.x = bfpack(r[0], r[1]); lv.y = bfpack(r[2], r[3]);
                lv.z = bfpack(r[4], r[5]); lv.w = bfpack(r[6], r[7]);
                *((uint4*)(Ahi + t * APITCH + j * 8)) = hv;
                *((uint4*)(Alo + t * APITCH + j * 8)) = lv;
            }
        }
        {
            size_t off = (size_t)wrow * KCONV + kb + kc * 64 + whalf * 32;
            const uint4* wh = (const uint4*)(g_Whi + off);
            const uint4* wl = (const uint4*)(g_Wlo + off);
            #pragma unroll
            for (int i = 0; i < 4; i++) {
                *((uint4*)(Whs + wrow * APITCH + whalf * 32 + i * 8)) = wh[i];
                *((uint4*)(Wls + wrow * APITCH + whalf * 32 + i * 8)) = wl[i];
            }
        }
        __syncthreads();

        #pragma unroll
        for (int s = 0; s < 4; s++) {
            const int k0 = s * 16;
            uint32_t ah[2][4], al[2][4];
            #pragma unroll
            for (int mt = 0; mt < 2; mt++) {
                int row = w * 32 + mt * 16 + a_row;
                uint32_t addr = sb + OFF_AHI + (uint32_t)(row * APITCH + a_col + k0) * 2;
                ldsm4(ah[mt], addr);
                addr = sb + OFF_ALO + (uint32_t)(row * APITCH + a_col + k0) * 2;
                ldsm4(al[mt], addr);
            }
            #pragma unroll
            for (int np = 0; np < 4; np++) {
                int n = np * 16 + b_n;
                uint32_t bh[4], bl[4];
                uint32_t addr = sb + OFF_WHI + (uint32_t)(n * APITCH + k0 + b_koff) * 2;
                ldsm4(bh, addr);
                addr = sb + OFF_WLO + (uint32_t)(n * APITCH + k0 + b_koff) * 2;
                ldsm4(bl, addr);
                #pragma unroll
                for (int mt = 0; mt < 2; mt++) {
                    #pragma unroll
                    for (int hh = 0; hh < 2; hh++) {
                        float* d = acc[mt][np * 2 + hh];
                        mma_bf16(d, ah[mt], bh + hh * 2);
                        mma_bf16(d, ah[mt], bl + hh * 2);
                        mma_bf16(d, al[mt], bh + hh * 2);
                    }
                }
            }
        }
        __syncthreads();
    }

    const int lr  = lane >> 2;
    const int lc2 = (lane & 3) << 1;
    #pragma unroll
    for (int mt = 0; mt < 2; mt++) {
        int row0 = w * 32 + mt * 16 + lr;
        #pragma unroll
        for (int nt = 0; nt < 8; nt++) {
            int col = nt * 8 + lc2;
            stg[col * SPITCH + row0]           = acc[mt][nt][0];
            stg[(col + 1) * SPITCH + row0]     = acc[mt][nt][1];
            stg[col * SPITCH + row0 + 8]       = acc[mt][nt][2];
            stg[(col + 1) * SPITCH + row0 + 8] = acc[mt][nt][3];
        }
    }
    __syncthreads();
    for (int i = t; i < 2048; i += 128) {
        int o = i >> 5, q = i & 31;
        float4 v = *((const float4*)(stg + o * SPITCH + q * 4));
        *((float4*)(g_part + ((size_t)kh * COUT + o) * PTOT + pbase + pl0 + q * 4)) = v;
    }
}

// ---------------------------------------------------------------------------
__global__ __launch_bounds__(256) void stats_kernel(
    const float* __restrict__ bconv,
    const float* __restrict__ gamma, const float* __restrict__ beta)
{
    const int o = blockIdx.x;
    const int t = threadIdx.x;
    const float4* r0 = (const float4*)(g_part + ((size_t)0 * COUT + o) * PTOT);
    const float4* r1 = (const float4*)(g_part + ((size_t)1 * COUT + o) * PTOT);
    const float4* r2 = (const float4*)(g_part + ((size_t)2 * COUT + o) * PTOT);
    const float4* r3 = (const float4*)(g_part + ((size_t)3 * COUT + o) * PTOT);
    float4*       pr = (float4*)(g_pre + (size_t)o * PTOT);
    const float bb = bconv[o];

    float s = 0.f, s2 = 0.f;
    for (int i = t; i < PTOT / 4; i += 256) {
        float4 a = r0[i], b = r1[i], c = r2[i], d = r3[i];
        float4 v;
        v.x = a.x + b.x + c.x + d.x + bb;
        v.y = a.y + b.y + c.y + d.y + bb;
        v.z = a.z + b.z + c.z + d.z + bb;
        v.w = a.w + b.w + c.w + d.w + bb;
        pr[i] = v;
        s  += v.x + v.y + v.z + v.w;
        s2 += v.x * v.x + v.y * v.y + v.z * v.z + v.w * v.w;
    }
    __shared__ float rs[256], rs2[256];
    rs[t] = s; rs2[t] = s2;
    __syncthreads();
    for (int st = 128; st > 0; st >>= 1) {
        if (t < st) { rs[t] += rs[t + st]; rs2[t] += rs2[t + st]; }
        __syncthreads();
    }
    if (t == 0) {
        float mean = rs[0] * (1.0f / PTOT);
        float var  = rs2[0] * (1.0f / PTOT) - mean * mean;
        float inv  = rsqrtf(var + 1e-5f);
        float sc   = gamma[o] * inv;
        g_scale[o] = sc;
        g_shift[o] = beta[o] - mean * sc;
    }
}

// ---------------------------------------------------------------------------
__global__ __launch_bounds__(256) void norm_kernel(float* __restrict__ out)
{
    int e = blockIdx.x * 256 + threadIdx.x;
    if (e >= BS * COUT * NPTS / 4) return;
    int nq = e & (NPTS / 4 - 1);
    int o  = (e >> 11) & 63;
    int b  = e >> 17;
    float4 v = *((const float4*)(g_pre + (size_t)o * PTOT + (b << 13)) + nq);
    float sc = g_scale[o], sh = g_shift[o];
    float4 r = make_float4(v.x * sc + sh, v.y * sc + sh, v.z * sc + sh, v.w * sc + sh);
    *((float4*)out + e) = r;
}

// ---------------------------------------------------------------------------
extern "C" void kernel_launch(void* const* d_in, const int* in_sizes, int n_in,
                              void* d_out, int out_size)
{
    const float* x     = (const float*)d_in[0];
    const float* feat  = (const float*)d_in[1];
    const int*   neigh = (const int*)  d_in[2];
    const float* Bmat  = (const float*)d_in[3];
    const float* kern  = (const float*)d_in[4];
    const float* onep  = (const float*)d_in[5];
    const float* Wmlp  = (const float*)d_in[6];
    const float* bmlp  = (const float*)d_in[7];
    const float* Wconv = (const float*)d_in[8];
    const float* bconv = (const float*)d_in[9];
    const float* gamma = (const float*)d_in[10];
    const float* beta  = (const float*)d_in[11];
    float* out = (float*)d_out;

    cudaFuncSetAttribute(gemm_kernel, cudaFuncAttributeMaxDynamicSharedMemorySize, GEMM_SMEM);

    prep_w<<<(COUT * KCONV + 255) / 256, 256>>>(Wconv);
    transpose_f<<<(BS * CIN * NPTS + 255) / 256, 256>>>(feat);
    transpose_x<<<(BS * 3 * NPTS + 255) / 256, 256>>>(x);
    for (int c = 0; c < NCHUNK; c++) {
        // neigh is indexed per-batch inside point_kernel via (pl+..)<<5 offsets
        point_kernel<<<CHUNK / PPB, 128>>>(c * CHUNK, neigh + (size_t)c * CHUNK * KNB,
                                           Bmat, kern, onep, Wmlp, bmlp);
        gemm_kernel<<<dim3(CHUNK / 128, KSPLIT), 128, GEMM_SMEM>>>(c * CHUNK);
    }
    stats_kernel<<<COUT, 256>>>(bconv, gamma, beta);
    norm_kernel<<<(BS * COUT * NPTS / 4 + 255) / 256, 256>>>(out);
}

// round 13
// speedup vs baseline: 1.9254x; 1.2269x over previous
#include <cuda_runtime.h>
#include <cuda_bf16.h>
#include <math.h>
#include <stdint.h>

#define BS     4
#define NPTS   8192
#define KNB    32
#define CIN    64
#define CX     32
#define CF     96
#define COUT   64
#define KCONV  3072
#define PTOT   32768
#define CHUNK  8192
#define NCHUNK (PTOT / CHUNK)
#define KSPLIT 4
#define KPART  (KCONV / KSPLIT)   // 768
#define PPB    8

// ---- device scratch (allocation-free) ----
__device__ float g_ft[BS * NPTS * CIN];
__device__ float g_xt[BS * NPTS * 4];
__device__ __nv_bfloat16 g_Ghi[(size_t)CHUNK * KCONV];   // feats hi (50 MB)
__device__ __nv_bfloat16 g_Glo[(size_t)CHUNK * KCONV];   // feats lo (50 MB)
__device__ float g_part[(size_t)KSPLIT * COUT * PTOT];
__device__ float g_pre[(size_t)COUT * PTOT];
__device__ float g_scale[COUT];
__device__ float g_shift[COUT];
__device__ __nv_bfloat16 g_Whi[(size_t)COUT * KCONV];
__device__ __nv_bfloat16 g_Wlo[(size_t)COUT * KCONV];

// ===========================================================================
__device__ __forceinline__ uint32_t smem_u32(const void* p) {
    uint32_t a;
    asm("{ .reg .u64 t; cvta.to.shared.u64 t, %1; cvt.u32.u64 %0, t; }" : "=r"(a) : "l"(p));
    return a;
}
__device__ __forceinline__ void ldsm4(uint32_t* r, uint32_t addr) {
    asm volatile("ldmatrix.sync.aligned.m8n8.x4.shared.b16 {%0,%1,%2,%3}, [%4];"
                 : "=r"(r[0]), "=r"(r[1]), "=r"(r[2]), "=r"(r[3]) : "r"(addr));
}
__device__ __forceinline__ void ldsm4t(uint32_t* r, uint32_t addr) {
    asm volatile("ldmatrix.sync.aligned.m8n8.x4.trans.shared.b16 {%0,%1,%2,%3}, [%4];"
                 : "=r"(r[0]), "=r"(r[1]), "=r"(r[2]), "=r"(r[3]) : "r"(addr));
}
__device__ __forceinline__ void ldsm2(uint32_t* r, uint32_t addr) {
    asm volatile("ldmatrix.sync.aligned.m8n8.x2.shared.b16 {%0,%1}, [%2];"
                 : "=r"(r[0]), "=r"(r[1]) : "r"(addr));
}
__device__ __forceinline__ void mma_bf16(float* d, const uint32_t* a, const uint32_t* b) {
    asm volatile(
        "mma.sync.aligned.m16n8k16.row.col.f32.bf16.bf16.f32 "
        "{%0,%1,%2,%3}, {%4,%5,%6,%7}, {%8,%9}, {%0,%1,%2,%3};"
        : "+f"(d[0]), "+f"(d[1]), "+f"(d[2]), "+f"(d[3])
        : "r"(a[0]), "r"(a[1]), "r"(a[2]), "r"(a[3]), "r"(b[0]), "r"(b[1]));
}
__device__ __forceinline__ void split2(float v0, float v1, uint32_t& hi, uint32_t& lo) {
    __nv_bfloat16 h0 = __float2bfloat16_rn(v0), h1 = __float2bfloat16_rn(v1);
    float l0 = v0 - __bfloat162float(h0);
    float l1 = v1 - __bfloat162float(h1);
    __nv_bfloat16 g0 = __float2bfloat16_rn(l0), g1 = __float2bfloat16_rn(l1);
    hi = ((uint32_t)__bfloat16_as_ushort(h1) << 16) | (uint32_t)__bfloat16_as_ushort(h0);
    lo = ((uint32_t)__bfloat16_as_ushort(g1) << 16) | (uint32_t)__bfloat16_as_ushort(g0);
}

// ---------------------------------------------------------------------------
__global__ __launch_bounds__(256) void prep_w(const float* __restrict__ Wconv)
{
    int e = blockIdx.x * 256 + threadIdx.x;
    if (e >= COUT * KCONV) return;
    float w = Wconv[e];
    __nv_bfloat16 hi = __float2bfloat16_rn(w);
    g_Whi[e] = hi;
    g_Wlo[e] = __float2bfloat16_rn(w - __bfloat162float(hi));
}

__global__ __launch_bounds__(256) void transpose_f(const float* __restrict__ f)
{
    int e = blockIdx.x * 256 + threadIdx.x;
    if (e >= BS * CIN * NPTS) return;
    int n = e & (NPTS - 1);
    int c = (e >> 13) & 63;
    int b = e >> 19;
    g_ft[(((size_t)(b << 13) + n) << 6) + c] = f[e];
}

__global__ __launch_bounds__(256) void transpose_x(const float* __restrict__ x)
{
    int e = blockIdx.x * 256 + threadIdx.x;
    if (e >= BS * 3 * NPTS) return;
    int b = e / (3 * NPTS);
    int r = e - b * 3 * NPTS;
    int d = r >> 13;
    int n = r & (NPTS - 1);
    g_xt[(((b << 13) + n) << 2) + d] = x[e];
}

// ---------------------------------------------------------------------------
// Per-point kernel v3: MLP + 96x32x32 contraction on HMMA (bf16 3-term split).
// A tile (feats) [k][c] bf16 hi/lo -> ldmatrix.x4.trans; B (raw perm) [j][k];
// normalization folded into epilogue; G stored pre-split bf16 hi/lo.
// ---------------------------------------------------------------------------
#define PA_PITCH 136
#define PB_PITCH 40
#define PE_PITCH 72

__global__ __launch_bounds__(128, 4) void point_kernel(
    int          pbase,
    const int*   __restrict__ neigh,
    const float* __restrict__ Bmat,
    const float* __restrict__ kern,
    const float* __restrict__ one_pad,
    const float* __restrict__ Wmlp,
    const float* __restrict__ bmlp)
{
    const int t    = threadIdx.x;
    const int lane = t & 31;
    const int w    = t >> 5;

    __shared__ uint16_t s_Ah[32][PA_PITCH], s_Al[32][PA_PITCH];   // feats [k][c]
    __shared__ uint16_t s_Bh[32][PB_PITCH], s_Bl[32][PB_PITCH];   // perm  [j][k]
    __shared__ uint16_t s_peh[32][PE_PITCH], s_pel[32][PE_PITCH]; // pe    [k][f]
    __shared__ uint16_t s_Wmh[32][PE_PITCH], s_Wml[32][PE_PITCH]; // Wmlp  [o][f]
    __shared__ float s_perm[32][33];
    __shared__ float s_B[7][32];
    __shared__ float s_k[3][32];
    __shared__ float s_bm[32];
    __shared__ float s_inv[32];

    for (int i = t; i < 224; i += 128) s_B[i >> 5][i & 31] = Bmat[i];
    for (int i = t; i < 96;  i += 128) s_k[i >> 5][i & 31] = kern[i];
    if (t < 32) s_bm[t] = bmlp[t];
    for (int i = t; i < 2048; i += 128) {
        int o = i >> 6, f = i & 63;
        float v = Wmlp[i];
        __nv_bfloat16 h = __float2bfloat16_rn(v);
        s_Wmh[o][f] = __bfloat16_as_ushort(h);
        s_Wml[o][f] = __bfloat16_as_ushort(__float2bfloat16_rn(v - __bfloat162float(h)));
    }
    float opr[8];
    #pragma unroll
    for (int i = 0; i < 8; i++) opr[i] = one_pad[lane * 32 + (w << 3) + i];

    const int    b   = pbase >> 13;
    const float* ftb = g_ft + ((size_t)b << 19);
    const float* xtb = g_xt + ((size_t)b << 15);
    const int    p0  = blockIdx.x * PPB;

    const int kr = t >> 4;
    const int c4 = t & 15;

    const uint32_t bAh = smem_u32(s_Ah), bAl = smem_u32(s_Al);
    const uint32_t bBh = smem_u32(s_Bh), bBl = smem_u32(s_Bl);
    const uint32_t bPh = smem_u32(s_peh), bPl = smem_u32(s_pel);
    const uint32_t bWh = smem_u32(s_Wmh), bWl = smem_u32(s_Wml);

    float4 fv[4];
    float4 xnl, xn0;
    {
        const int pb5 = p0 << 5;
        int i0 = neigh[pb5];
        int il = neigh[pb5 + lane];
        xn0 = *((const float4*)(xtb + ((size_t)i0 << 2)));
        xnl = *((const float4*)(xtb + ((size_t)il << 2)));
        #pragma unroll
        for (int r = 0; r < 4; r++) {
            int idx = neigh[pb5 + kr + r * 8];
            fv[r] = *((const float4*)(ftb + ((size_t)idx << 6) + (c4 << 2)));
        }
    }
    __syncthreads();

    const float TWO_PI = 6.283185307179586f;

    for (int ip = 0; ip < PPB; ip++) {
        const int pl = p0 + ip;

        // ======== write phase ========
        #pragma unroll
        for (int r = 0; r < 4; r++) {
            const int k = kr + r * 8;
            uint32_t h0, l0, h1, l1;
            split2(fv[r].x, fv[r].y, h0, l0);
            split2(fv[r].z, fv[r].w, h1, l1);
            *((uint2*)&s_Ah[k][c4 << 2]) = make_uint2(h0, h1);
            *((uint2*)&s_Al[k][c4 << 2]) = make_uint2(l0, l1);
        }

        const float r0 = xnl.x - xn0.x;
        const float r1 = xnl.y - xn0.y;
        const float r2 = xnl.z - xn0.z;
        const float dis = sqrtf(fmaxf(r0 * r0 + r1 * r1 + r2 * r2, 1e-12f));

        {
            float sv[8], cv[8];
            #pragma unroll
            for (int i = 0; i < 8; i++) {
                const int m = (w << 3) + i;
                float acc = xn0.x * s_B[0][m] + xn0.y * s_B[1][m] + xn0.z * s_B[2][m]
                          + r0 * s_B[3][m] + r1 * s_B[4][m] + r2 * s_B[5][m]
                          + dis * s_B[6][m];
                __sincosf(acc * TWO_PI, &sv[i], &cv[i]);
            }
            #pragma unroll
            for (int i = 0; i < 8; i += 2) {
                uint32_t h, l;
                split2(sv[i], sv[i + 1], h, l);
                *((uint32_t*)&s_peh[lane][(w << 3) + i]) = h;
                *((uint32_t*)&s_pel[lane][(w << 3) + i]) = l;
                split2(cv[i], cv[i + 1], h, l);
                *((uint32_t*)&s_peh[lane][32 + (w << 3) + i]) = h;
                *((uint32_t*)&s_pel[lane][32 + (w << 3) + i]) = l;
            }
        }

        #pragma unroll
        for (int i = 0; i < 8; i++) {
            const int j = (w << 3) + i;
            float v = fmaxf(opr[i] + r0 * s_k[0][j] + r1 * s_k[1][j] + r2 * s_k[2][j], 0.0f);
            s_perm[lane][j] = v;
            __nv_bfloat16 h = __float2bfloat16_rn(v);
            s_Bh[j][lane] = __bfloat16_as_ushort(h);
            s_Bl[j][lane] = __bfloat16_as_ushort(__float2bfloat16_rn(v - __bfloat162float(h)));
        }
        __syncthreads();   // sync1

        // ======== MLP via HMMA: x_feats[k][o], warp w -> o octet ========
        {
            float d0[4] = {0.f, 0.f, 0.f, 0.f};
            float d1[4] = {0.f, 0.f, 0.f, 0.f};
            const int arow = lane & 15;
            const int acol = (lane >> 4) << 3;
            const int bl15 = lane & 15;
            const uint32_t brow = (uint32_t)((w << 3) + (bl15 & 7));
            const uint32_t bkof = (uint32_t)(((bl15 >> 3) & 1) << 3);
            #pragma unroll
            for (int kh = 0; kh < 4; kh++) {
                const uint32_t boff = (brow * PE_PITCH + kh * 16 + bkof) * 2;
                uint32_t bh[2], bl[2];
                ldsm2(bh, bWh + boff);
                ldsm2(bl, bWl + boff);
                #pragma unroll
                for (int mt = 0; mt < 2; mt++) {
                    uint32_t ah[4], al[4];
                    const uint32_t aoff = (uint32_t)((mt * 16 + arow) * PE_PITCH + kh * 16 + acol) * 2;
                    ldsm4(ah, bPh + aoff);
                    ldsm4(al, bPl + aoff);
                    float* d = mt ? d1 : d0;
                    mma_bf16(d, ah, bh);
                    mma_bf16(d, ah, bl);
                    mma_bf16(d, al, bh);
                }
            }
            const int o = (w << 3) + ((lane & 3) << 1);
            const float bb0 = s_bm[o], bb1 = s_bm[o + 1];
            #pragma unroll
            for (int mt = 0; mt < 2; mt++) {
                const float* d = mt ? d1 : d0;
                const int krow = mt * 16 + (lane >> 2);
                uint32_t h, l;
                split2(d[0] + bb0, d[1] + bb1, h, l);
                *((uint32_t*)&s_Ah[krow][64 + o]) = h;
                *((uint32_t*)&s_Al[krow][64 + o]) = l;
                split2(d[2] + bb0, d[3] + bb1, h, l);
                *((uint32_t*)&s_Ah[krow + 8][64 + o]) = h;
                *((uint32_t*)&s_Al[krow + 8][64 + o]) = l;
            }
        }

        if (t < 32) {
            float s = 0.f;
            #pragma unroll
            for (int k = 0; k < 32; k++) s += s_perm[k][t];
            s_inv[t] = 1.0f / (s + 1e-6f);
        }

        if (ip + 1 < PPB) {
            const int pb5 = (pl + 1) << 5;
            int i0 = neigh[pb5];
            int il = neigh[pb5 + lane];
            xn0 = *((const float4*)(xtb + ((size_t)i0 << 2)));
            xnl = *((const float4*)(xtb + ((size_t)il << 2)));
            #pragma unroll
            for (int r = 0; r < 4; r++) {
                int idx = neigh[pb5 + kr + r * 8];
                fv[r] = *((const float4*)(ftb + ((size_t)idx << 6) + (c4 << 2)));
            }
        }
        __syncthreads();   // sync2

        // ======== contraction via HMMA: warps 0..2, c = w*32..+31 ========
        if (w < 3) {
            float acc[2][4][4];
            #pragma unroll
            for (int mt = 0; mt < 2; mt++)
                #pragma unroll
                for (int nt = 0; nt < 4; nt++)
                    #pragma unroll
                    for (int i = 0; i < 4; i++) acc[mt][nt][i] = 0.f;

            const uint32_t a_krow = (uint32_t)((lane & 7) + ((lane >> 4) << 3));
            const uint32_t a_cblk = (uint32_t)(((lane >> 3) & 1) << 3);
            const uint32_t b_n    = (uint32_t)((lane & 7) + (((lane >> 4) & 1) << 3));
            const uint32_t b_koff = (uint32_t)(((lane >> 3) & 1) << 3);

            #pragma unroll
            for (int kh = 0; kh < 2; kh++) {
                const uint32_t k0 = kh * 16;
                #pragma unroll
                for (int mt = 0; mt < 2; mt++) {
                    uint32_t ah[4], al[4];
                    const uint32_t cb = (uint32_t)(w * 32 + mt * 16) + a_cblk;
                    const uint32_t aoff = ((k0 + a_krow) * PA_PITCH + cb) * 2;
                    ldsm4t(ah, bAh + aoff);
                    ldsm4t(al, bAl + aoff);
                    #pragma unroll
                    for (int bt = 0; bt < 2; bt++) {
                        uint32_t bh[4], bl[4];
                        const uint32_t boff = (((uint32_t)(bt * 16) + b_n) * PB_PITCH + k0 + b_koff) * 2;
                        ldsm4(bh, bBh + boff);
                        ldsm4(bl, bBl + boff);
                        #pragma unroll
                        for (int hh = 0; hh < 2; hh++) {
                            float* d = acc[mt][bt * 2 + hh];
                            mma_bf16(d, ah, bh + hh * 2);
                            mma_bf16(d, ah, bl + hh * 2);
                            mma_bf16(d, al, bh + hh * 2);
                        }
                    }
                }
            }

            __nv_bfloat16* gh = g_Ghi + (size_t)pl * KCONV;
            __nv_bfloat16* gl = g_Glo + (size_t)pl * KCONV;
            #pragma unroll
            for (int nt = 0; nt < 4; nt++) {
                const int j = nt * 8 + ((lane & 3) << 1);
                const float i0 = s_inv[j], i1 = s_inv[j + 1];
                #pragma unroll
                for (int mt = 0; mt < 2; mt++) {
                    const float* d = acc[mt][nt];
                    const int c0 = w * 32 + mt * 16 + (lane >> 2);
                    uint32_t h, l;
                    split2(d[0] * i0, d[1] * i1, h, l);
                    *((uint32_t*)(gh + c0 * 32 + j)) = h;
                    *((uint32_t*)(gl + c0 * 32 + j)) = l;
                    split2(d[2] * i0, d[3] * i1, h, l);
                    *((uint32_t*)(gh + (c0 + 8) * 32 + j)) = h;
                    *((uint32_t*)(gl + (c0 + 8) * 32 + j)) = l;
                }
            }
        }
        __syncthreads();   // sync3
    }
}

// ---------------------------------------------------------------------------
// bf16 3-term GEMM via mma.sync — converter removed (G pre-split in gmem).
// ---------------------------------------------------------------------------
#define OFF_AHI 0
#define OFF_ALO 18432
#define OFF_WHI 36864
#define OFF_WLO 46080
#define GEMM_SMEM 55296
#define APITCH 72
#define SPITCH 132

__global__ __launch_bounds__(128) void gemm_kernel(int pbase)
{
    extern __shared__ char smem[];
    __nv_bfloat16* Ahi = (__nv_bfloat16*)(smem + OFF_AHI);
    __nv_bfloat16* Alo = (__nv_bfloat16*)(smem + OFF_ALO);
    __nv_bfloat16* Whs = (__nv_bfloat16*)(smem + OFF_WHI);
    __nv_bfloat16* Wls = (__nv_bfloat16*)(smem + OFF_WLO);
    float*         stg = (float*)smem;
    const uint32_t sb  = smem_u32(smem);

    const int t    = threadIdx.x;
    const int lane = t & 31;
    const int w    = t >> 5;
    const int pl0  = blockIdx.x * 128;
    const int kh   = blockIdx.y;
    const int kb   = kh * KPART;

    float acc[2][8][4];
    #pragma unroll
    for (int mt = 0; mt < 2; mt++)
        #pragma unroll
        for (int nt = 0; nt < 8; nt++)
            #pragma unroll
            for (int i = 0; i < 4; i++) acc[mt][nt][i] = 0.f;

    const int wrow  = t >> 1;
    const int whalf = t & 1;

    const int a_row  = (lane & 15);
    const int a_col  = (lane >> 4) << 3;
    const int b_n    = (lane & 7) + (((lane >> 4) & 1) << 3);
    const int b_koff = ((lane >> 3) & 1) << 3;

    for (int kc = 0; kc < KPART / 64; kc++) {
        {
            const uint4* sh = (const uint4*)(g_Ghi + (size_t)(pl0 + t) * KCONV + kb + kc * 64);
            const uint4* sl = (const uint4*)(g_Glo + (size_t)(pl0 + t) * KCONV + kb + kc * 64);
            #pragma unroll
            for (int j = 0; j < 8; j++) {
                *((uint4*)(Ahi + t * APITCH + j * 8)) = sh[j];
                *((uint4*)(Alo + t * APITCH + j * 8)) = sl[j];
            }
        }
        {
            size_t off = (size_t)wrow * KCONV + kb + kc * 64 + whalf * 32;
            const uint4* wh = (const uint4*)(g_Whi + off);
            const uint4* wl = (const uint4*)(g_Wlo + off);
            #pragma unroll
            for (int i = 0; i < 4; i++) {
                *((uint4*)(Whs + wrow * APITCH + whalf * 32 + i * 8)) = wh[i];
                *((uint4*)(Wls + wrow * APITCH + whalf * 32 + i * 8)) = wl[i];
            }
        }
        __syncthreads();

        #pragma unroll
        for (int s = 0; s < 4; s++) {
            const int k0 = s * 16;
            uint32_t ah[2][4], al[2][4];
            #pragma unroll
            for (int mt = 0; mt < 2; mt++) {
                int row = w * 32 + mt * 16 + a_row;
                uint32_t addr = sb + OFF_AHI + (uint32_t)(row * APITCH + a_col + k0) * 2;
                ldsm4(ah[mt], addr);
                addr = sb + OFF_ALO + (uint32_t)(row * APITCH + a_col + k0) * 2;
                ldsm4(al[mt], addr);
            }
            #pragma unroll
            for (int np = 0; np < 4; np++) {
                int n = np * 16 + b_n;
                uint32_t bh[4], bl[4];
                uint32_t addr = sb + OFF_WHI + (uint32_t)(n * APITCH + k0 + b_koff) * 2;
                ldsm4(bh, addr);
                addr = sb + OFF_WLO + (uint32_t)(n * APITCH + k0 + b_koff) * 2;
                ldsm4(bl, addr);
                #pragma unroll
                for (int mt = 0; mt < 2; mt++) {
                    #pragma unroll
                    for (int hh = 0; hh < 2; hh++) {
                        float* d = acc[mt][np * 2 + hh];
                        mma_bf16(d, ah[mt], bh + hh * 2);
                        mma_bf16(d, ah[mt], bl + hh * 2);
                        mma_bf16(d, al[mt], bh + hh * 2);
                    }
                }
            }
        }
        __syncthreads();
    }

    const int lr  = lane >> 2;
    const int lc2 = (lane & 3) << 1;
    #pragma unroll
    for (int mt = 0; mt < 2; mt++) {
        int row0 = w * 32 + mt * 16 + lr;
        #pragma unroll
        for (int nt = 0; nt < 8; nt++) {
            int col = nt * 8 + lc2;
            stg[col * SPITCH + row0]           = acc[mt][nt][0];
            stg[(col + 1) * SPITCH + row0]     = acc[mt][nt][1];
            stg[col * SPITCH + row0 + 8]       = acc[mt][nt][2];
            stg[(col + 1) * SPITCH + row0 + 8] = acc[mt][nt][3];
        }
    }
    __syncthreads();
    for (int i = t; i < 2048; i += 128) {
        int o = i >> 5, q = i & 31;
        float4 v = *((const float4*)(stg + o * SPITCH + q * 4));
        *((float4*)(g_part + ((size_t)kh * COUT + o) * PTOT + pbase + pl0 + q * 4)) = v;
    }
}

// ---------------------------------------------------------------------------
__global__ __launch_bounds__(256) void stats_kernel(
    const float* __restrict__ bconv,
    const float* __restrict__ gamma, const float* __restrict__ beta)
{
    const int o = blockIdx.x;
    const int t = threadIdx.x;
    const float4* r0 = (const float4*)(g_part + ((size_t)0 * COUT + o) * PTOT);
    const float4* r1 = (const float4*)(g_part + ((size_t)1 * COUT + o) * PTOT);
    const float4* r2 = (const float4*)(g_part + ((size_t)2 * COUT + o) * PTOT);
    const float4* r3 = (const float4*)(g_part + ((size_t)3 * COUT + o) * PTOT);
    float4*       pr = (float4*)(g_pre + (size_t)o * PTOT);
    const float bb = bconv[o];

    float s = 0.f, s2 = 0.f;
    for (int i = t; i < PTOT / 4; i += 256) {
        float4 a = r0[i], b = r1[i], c = r2[i], d = r3[i];
        float4 v;
        v.x = a.x + b.x + c.x + d.x + bb;
        v.y = a.y + b.y + c.y + d.y + bb;
        v.z = a.z + b.z + c.z + d.z + bb;
        v.w = a.w + b.w + c.w + d.w + bb;
        pr[i] = v;
        s  += v.x + v.y + v.z + v.w;
        s2 += v.x * v.x + v.y * v.y + v.z * v.z + v.w * v.w;
    }
    __shared__ float rs[256], rs2[256];
    rs[t] = s; rs2[t] = s2;
    __syncthreads();
    for (int st = 128; st > 0; st >>= 1) {
        if (t < st) { rs[t] += rs[t + st]; rs2[t] += rs2[t + st]; }
        __syncthreads();
    }
    if (t == 0) {
        float mean = rs[0] * (1.0f / PTOT);
        float var  = rs2[0] * (1.0f / PTOT) - mean * mean;
        float inv  = rsqrtf(var + 1e-5f);
        float sc   = gamma[o] * inv;
        g_scale[o] = sc;
        g_shift[o] = beta[o] - mean * sc;
    }
}

// ---------------------------------------------------------------------------
__global__ __launch_bounds__(256) void norm_kernel(float* __restrict__ out)
{
    int e = blockIdx.x * 256 + threadIdx.x;
    if (e >= BS * COUT * NPTS / 4) return;
    int nq = e & (NPTS / 4 - 1);
    int o  = (e >> 11) & 63;
    int b  = e >> 17;
    float4 v = *((const float4*)(g_pre + (size_t)o * PTOT + (b << 13)) + nq);
    float sc = g_scale[o], sh = g_shift[o];
    float4 r = make_float4(v.x * sc + sh, v.y * sc + sh, v.z * sc + sh, v.w * sc + sh);
    *((float4*)out + e) = r;
}

// ---------------------------------------------------------------------------
extern "C" void kernel_launch(void* const* d_in, const int* in_sizes, int n_in,
                              void* d_out, int out_size)
{
    const float* x     = (const float*)d_in[0];
    const float* feat  = (const float*)d_in[1];
    const int*   neigh = (const int*)  d_in[2];
    const float* Bmat  = (const float*)d_in[3];
    const float* kern  = (const float*)d_in[4];
    const float* onep  = (const float*)d_in[5];
    const float* Wmlp  = (const float*)d_in[6];
    const float* bmlp  = (const float*)d_in[7];
    const float* Wconv = (const float*)d_in[8];
    const float* bconv = (const float*)d_in[9];
    const float* gamma = (const float*)d_in[10];
    const float* beta  = (const float*)d_in[11];
    float* out = (float*)d_out;

    cudaFuncSetAttribute(gemm_kernel, cudaFuncAttributeMaxDynamicSharedMemorySize, GEMM_SMEM);

    prep_w<<<(COUT * KCONV + 255) / 256, 256>>>(Wconv);
    transpose_f<<<(BS * CIN * NPTS + 255) / 256, 256>>>(feat);
    transpose_x<<<(BS * 3 * NPTS + 255) / 256, 256>>>(x);
    for (int c = 0; c < NCHUNK; c++) {
        point_kernel<<<CHUNK / PPB, 128>>>(c * CHUNK, neigh + (size_t)c * CHUNK * KNB,
                                           Bmat, kern, onep, Wmlp, bmlp);
        gemm_kernel<<<dim3(CHUNK / 128, KSPLIT), 128, GEMM_SMEM>>>(c * CHUNK);
    }
    stats_kernel<<<COUT, 256>>>(bconv, gamma, beta);
    norm_kernel<<<(BS * COUT * NPTS / 4 + 255) / 256, 256>>>(out);
}

// round 14
// speedup vs baseline: 2.0031x; 1.0403x over previous
#include <cuda_runtime.h>
#include <cuda_bf16.h>
#include <math.h>
#include <stdint.h>

#define BS     4
#define NPTS   8192
#define KNB    32
#define CIN    64
#define CX     32
#define CF     96
#define COUT   64
#define KCONV  3072
#define PTOT   32768
#define CHUNK  8192
#define NCHUNK (PTOT / CHUNK)
#define KSPLIT 4
#define KPART  (KCONV / KSPLIT)   // 768
#define PPB    8

// ---- device scratch (allocation-free) ----
__device__ float g_ft[BS * NPTS * CIN];
__device__ float g_xt[BS * NPTS * 4];
__device__ __nv_bfloat16 g_Ghi[(size_t)CHUNK * KCONV];   // feats hi (50 MB)
__device__ __nv_bfloat16 g_Glo[(size_t)CHUNK * KCONV];   // feats lo (50 MB)
__device__ float g_part[(size_t)KSPLIT * COUT * PTOT];
__device__ float g_pre[(size_t)COUT * PTOT];
__device__ float g_scale[COUT];
__device__ float g_shift[COUT];
__device__ __nv_bfloat16 g_Whi[(size_t)COUT * KCONV];
__device__ __nv_bfloat16 g_Wlo[(size_t)COUT * KCONV];

// ===========================================================================
__device__ __forceinline__ uint32_t smem_u32(const void* p) {
    uint32_t a;
    asm("{ .reg .u64 t; cvta.to.shared.u64 t, %1; cvt.u32.u64 %0, t; }" : "=r"(a) : "l"(p));
    return a;
}
__device__ __forceinline__ void ldsm4(uint32_t* r, uint32_t addr) {
    asm volatile("ldmatrix.sync.aligned.m8n8.x4.shared.b16 {%0,%1,%2,%3}, [%4];"
                 : "=r"(r[0]), "=r"(r[1]), "=r"(r[2]), "=r"(r[3]) : "r"(addr));
}
__device__ __forceinline__ void ldsm4t(uint32_t* r, uint32_t addr) {
    asm volatile("ldmatrix.sync.aligned.m8n8.x4.trans.shared.b16 {%0,%1,%2,%3}, [%4];"
                 : "=r"(r[0]), "=r"(r[1]), "=r"(r[2]), "=r"(r[3]) : "r"(addr));
}
__device__ __forceinline__ void ldsm2(uint32_t* r, uint32_t addr) {
    asm volatile("ldmatrix.sync.aligned.m8n8.x2.shared.b16 {%0,%1}, [%2];"
                 : "=r"(r[0]), "=r"(r[1]) : "r"(addr));
}
__device__ __forceinline__ void mma_bf16(float* d, const uint32_t* a, const uint32_t* b) {
    asm volatile(
        "mma.sync.aligned.m16n8k16.row.col.f32.bf16.bf16.f32 "
        "{%0,%1,%2,%3}, {%4,%5,%6,%7}, {%8,%9}, {%0,%1,%2,%3};"
        : "+f"(d[0]), "+f"(d[1]), "+f"(d[2]), "+f"(d[3])
        : "r"(a[0]), "r"(a[1]), "r"(a[2]), "r"(a[3]), "r"(b[0]), "r"(b[1]));
}
__device__ __forceinline__ void split2(float v0, float v1, uint32_t& hi, uint32_t& lo) {
    __nv_bfloat16 h0 = __float2bfloat16_rn(v0), h1 = __float2bfloat16_rn(v1);
    float l0 = v0 - __bfloat162float(h0);
    float l1 = v1 - __bfloat162float(h1);
    __nv_bfloat16 g0 = __float2bfloat16_rn(l0), g1 = __float2bfloat16_rn(l1);
    hi = ((uint32_t)__bfloat16_as_ushort(h1) << 16) | (uint32_t)__bfloat16_as_ushort(h0);
    lo = ((uint32_t)__bfloat16_as_ushort(g1) << 16) | (uint32_t)__bfloat16_as_ushort(g0);
}
__device__ __forceinline__ void cp16(uint32_t saddr, const void* gaddr) {
    asm volatile("cp.async.cg.shared.global [%0], [%1], 16;"
                 :: "r"(saddr), "l"(gaddr) : "memory");
}
#define CP_COMMIT() asm volatile("cp.async.commit_group;" ::: "memory")
#define CP_WAIT(n)  asm volatile("cp.async.wait_group %0;" :: "n"(n) : "memory")

// ---------------------------------------------------------------------------
__global__ __launch_bounds__(256) void prep_w(const float* __restrict__ Wconv)
{
    int e = blockIdx.x * 256 + threadIdx.x;
    if (e >= COUT * KCONV) return;
    float w = Wconv[e];
    __nv_bfloat16 hi = __float2bfloat16_rn(w);
    g_Whi[e] = hi;
    g_Wlo[e] = __float2bfloat16_rn(w - __bfloat162float(hi));
}

__global__ __launch_bounds__(256) void transpose_f(const float* __restrict__ f)
{
    int e = blockIdx.x * 256 + threadIdx.x;
    if (e >= BS * CIN * NPTS) return;
    int n = e & (NPTS - 1);
    int c = (e >> 13) & 63;
    int b = e >> 19;
    g_ft[(((size_t)(b << 13) + n) << 6) + c] = f[e];
}

__global__ __launch_bounds__(256) void transpose_x(const float* __restrict__ x)
{
    int e = blockIdx.x * 256 + threadIdx.x;
    if (e >= BS * 3 * NPTS) return;
    int b = e / (3 * NPTS);
    int r = e - b * 3 * NPTS;
    int d = r >> 13;
    int n = r & (NPTS - 1);
    g_xt[(((b << 13) + n) << 2) + d] = x[e];
}

// ---------------------------------------------------------------------------
// Per-point kernel: MLP + 96x32x32 contraction on HMMA (bf16 3-term split).
// PA_PITCH 104 (conflict-free for ldsm4t) -> 41.6 KB static smem -> 5 CTAs/SM.
// ---------------------------------------------------------------------------
#define PA_PITCH 104
#define PB_PITCH 40
#define PE_PITCH 72

__global__ __launch_bounds__(128, 5) void point_kernel(
    int          pbase,
    const int*   __restrict__ neigh,
    const float* __restrict__ Bmat,
    const float* __restrict__ kern,
    const float* __restrict__ one_pad,
    const float* __restrict__ Wmlp,
    const float* __restrict__ bmlp)
{
    const int t    = threadIdx.x;
    const int lane = t & 31;
    const int w    = t >> 5;

    __shared__ uint16_t s_Ah[32][PA_PITCH], s_Al[32][PA_PITCH];   // feats [k][c]
    __shared__ uint16_t s_Bh[32][PB_PITCH], s_Bl[32][PB_PITCH];   // perm  [j][k]
    __shared__ uint16_t s_peh[32][PE_PITCH], s_pel[32][PE_PITCH]; // pe    [k][f]
    __shared__ uint16_t s_Wmh[32][PE_PITCH], s_Wml[32][PE_PITCH]; // Wmlp  [o][f]
    __shared__ float s_perm[32][33];
    __shared__ float s_B[7][32];
    __shared__ float s_k[3][32];
    __shared__ float s_bm[32];
    __shared__ float s_inv[32];

    for (int i = t; i < 224; i += 128) s_B[i >> 5][i & 31] = Bmat[i];
    for (int i = t; i < 96;  i += 128) s_k[i >> 5][i & 31] = kern[i];
    if (t < 32) s_bm[t] = bmlp[t];
    for (int i = t; i < 2048; i += 128) {
        int o = i >> 6, f = i & 63;
        float v = Wmlp[i];
        __nv_bfloat16 h = __float2bfloat16_rn(v);
        s_Wmh[o][f] = __bfloat16_as_ushort(h);
        s_Wml[o][f] = __bfloat16_as_ushort(__float2bfloat16_rn(v - __bfloat162float(h)));
    }
    float opr[8];
    #pragma unroll
    for (int i = 0; i < 8; i++) opr[i] = one_pad[lane * 32 + (w << 3) + i];

    const int    b   = pbase >> 13;
    const float* ftb = g_ft + ((size_t)b << 19);
    const float* xtb = g_xt + ((size_t)b << 15);
    const int    p0  = blockIdx.x * PPB;

    const int kr = t >> 4;
    const int c4 = t & 15;

    const uint32_t bAh = smem_u32(s_Ah), bAl = smem_u32(s_Al);
    const uint32_t bBh = smem_u32(s_Bh), bBl = smem_u32(s_Bl);
    const uint32_t bPh = smem_u32(s_peh), bPl = smem_u32(s_pel);
    const uint32_t bWh = smem_u32(s_Wmh), bWl = smem_u32(s_Wml);

    float4 fv[4];
    float4 xnl, xn0;
    {
        const int pb5 = p0 << 5;
        int i0 = neigh[pb5];
        int il = neigh[pb5 + lane];
        xn0 = *((const float4*)(xtb + ((size_t)i0 << 2)));
        xnl = *((const float4*)(xtb + ((size_t)il << 2)));
        #pragma unroll
        for (int r = 0; r < 4; r++) {
            int idx = neigh[pb5 + kr + r * 8];
            fv[r] = *((const float4*)(ftb + ((size_t)idx << 6) + (c4 << 2)));
        }
    }
    __syncthreads();

    const float TWO_PI = 6.283185307179586f;

    for (int ip = 0; ip < PPB; ip++) {
        const int pl = p0 + ip;

        // ======== write phase ========
        #pragma unroll
        for (int r = 0; r < 4; r++) {
            const int k = kr + r * 8;
            uint32_t h0, l0, h1, l1;
            split2(fv[r].x, fv[r].y, h0, l0);
            split2(fv[r].z, fv[r].w, h1, l1);
            *((uint2*)&s_Ah[k][c4 << 2]) = make_uint2(h0, h1);
            *((uint2*)&s_Al[k][c4 << 2]) = make_uint2(l0, l1);
        }

        const float r0 = xnl.x - xn0.x;
        const float r1 = xnl.y - xn0.y;
        const float r2 = xnl.z - xn0.z;
        const float dis = sqrtf(fmaxf(r0 * r0 + r1 * r1 + r2 * r2, 1e-12f));

        {
            float sv[8], cv[8];
            #pragma unroll
            for (int i = 0; i < 8; i++) {
                const int m = (w << 3) + i;
                float acc = xn0.x * s_B[0][m] + xn0.y * s_B[1][m] + xn0.z * s_B[2][m]
                          + r0 * s_B[3][m] + r1 * s_B[4][m] + r2 * s_B[5][m]
                          + dis * s_B[6][m];
                __sincosf(acc * TWO_PI, &sv[i], &cv[i]);
            }
            #pragma unroll
            for (int i = 0; i < 8; i += 2) {
                uint32_t h, l;
                split2(sv[i], sv[i + 1], h, l);
                *((uint32_t*)&s_peh[lane][(w << 3) + i]) = h;
                *((uint32_t*)&s_pel[lane][(w << 3) + i]) = l;
                split2(cv[i], cv[i + 1], h, l);
                *((uint32_t*)&s_peh[lane][32 + (w << 3) + i]) = h;
                *((uint32_t*)&s_pel[lane][32 + (w << 3) + i]) = l;
            }
        }

        #pragma unroll
        for (int i = 0; i < 8; i++) {
            const int j = (w << 3) + i;
            float v = fmaxf(opr[i] + r0 * s_k[0][j] + r1 * s_k[1][j] + r2 * s_k[2][j], 0.0f);
            s_perm[lane][j] = v;
            __nv_bfloat16 h = __float2bfloat16_rn(v);
            s_Bh[j][lane] = __bfloat16_as_ushort(h);
            s_Bl[j][lane] = __bfloat16_as_ushort(__float2bfloat16_rn(v - __bfloat162float(h)));
        }
        __syncthreads();   // sync1

        // ======== MLP via HMMA ========
        {
            float d0[4] = {0.f, 0.f, 0.f, 0.f};
            float d1[4] = {0.f, 0.f, 0.f, 0.f};
            const int arow = lane & 15;
            const int acol = (lane >> 4) << 3;
            const int bl15 = lane & 15;
            const uint32_t brow = (uint32_t)((w << 3) + (bl15 & 7));
            const uint32_t bkof = (uint32_t)(((bl15 >> 3) & 1) << 3);
            #pragma unroll
            for (int kh = 0; kh < 4; kh++) {
                const uint32_t boff = (brow * PE_PITCH + kh * 16 + bkof) * 2;
                uint32_t bh[2], bl[2];
                ldsm2(bh, bWh + boff);
                ldsm2(bl, bWl + boff);
                #pragma unroll
                for (int mt = 0; mt < 2; mt++) {
                    uint32_t ah[4], al[4];
                    const uint32_t aoff = (uint32_t)((mt * 16 + arow) * PE_PITCH + kh * 16 + acol) * 2;
                    ldsm4(ah, bPh + aoff);
                    ldsm4(al, bPl + aoff);
                    float* d = mt ? d1 : d0;
                    mma_bf16(d, ah, bh);
                    mma_bf16(d, ah, bl);
                    mma_bf16(d, al, bh);
                }
            }
            const int o = (w << 3) + ((lane & 3) << 1);
            const float bb0 = s_bm[o], bb1 = s_bm[o + 1];
            #pragma unroll
            for (int mt = 0; mt < 2; mt++) {
                const float* d = mt ? d1 : d0;
                const int krow = mt * 16 + (lane >> 2);
                uint32_t h, l;
                split2(d[0] + bb0, d[1] + bb1, h, l);
                *((uint32_t*)&s_Ah[krow][64 + o]) = h;
                *((uint32_t*)&s_Al[krow][64 + o]) = l;
                split2(d[2] + bb0, d[3] + bb1, h, l);
                *((uint32_t*)&s_Ah[krow + 8][64 + o]) = h;
                *((uint32_t*)&s_Al[krow + 8][64 + o]) = l;
            }
        }

        if (t < 32) {
            float s = 0.f;
            #pragma unroll
            for (int k = 0; k < 32; k++) s += s_perm[k][t];
            s_inv[t] = 1.0f / (s + 1e-6f);
        }

        if (ip + 1 < PPB) {
            const int pb5 = (pl + 1) << 5;
            int i0 = neigh[pb5];
            int il = neigh[pb5 + lane];
            xn0 = *((const float4*)(xtb + ((size_t)i0 << 2)));
            xnl = *((const float4*)(xtb + ((size_t)il << 2)));
            #pragma unroll
            for (int r = 0; r < 4; r++) {
                int idx = neigh[pb5 + kr + r * 8];
                fv[r] = *((const float4*)(ftb + ((size_t)idx << 6) + (c4 << 2)));
            }
        }
        __syncthreads();   // sync2

        // ======== contraction via HMMA: warps 0..2, c = w*32..+31 ========
        if (w < 3) {
            float acc[2][4][4];
            #pragma unroll
            for (int mt = 0; mt < 2; mt++)
                #pragma unroll
                for (int nt = 0; nt < 4; nt++)
                    #pragma unroll
                    for (int i = 0; i < 4; i++) acc[mt][nt][i] = 0.f;

            const uint32_t a_krow = (uint32_t)((lane & 7) + ((lane >> 4) << 3));
            const uint32_t a_cblk = (uint32_t)(((lane >> 3) & 1) << 3);
            const uint32_t b_n    = (uint32_t)((lane & 7) + (((lane >> 4) & 1) << 3));
            const uint32_t b_koff = (uint32_t)(((lane >> 3) & 1) << 3);

            #pragma unroll
            for (int kh = 0; kh < 2; kh++) {
                const uint32_t k0 = kh * 16;
                #pragma unroll
                for (int mt = 0; mt < 2; mt++) {
                    uint32_t ah[4], al[4];
                    const uint32_t cb = (uint32_t)(w * 32 + mt * 16) + a_cblk;
                    const uint32_t aoff = ((k0 + a_krow) * PA_PITCH + cb) * 2;
                    ldsm4t(ah, bAh + aoff);
                    ldsm4t(al, bAl + aoff);
                    #pragma unroll
                    for (int bt = 0; bt < 2; bt++) {
                        uint32_t bh[4], bl[4];
                        const uint32_t boff = (((uint32_t)(bt * 16) + b_n) * PB_PITCH + k0 + b_koff) * 2;
                        ldsm4(bh, bBh + boff);
                        ldsm4(bl, bBl + boff);
                        #pragma unroll
                        for (int hh = 0; hh < 2; hh++) {
                            float* d = acc[mt][bt * 2 + hh];
                            mma_bf16(d, ah, bh + hh * 2);
                            mma_bf16(d, ah, bl + hh * 2);
                            mma_bf16(d, al, bh + hh * 2);
                        }
                    }
                }
            }

            __nv_bfloat16* gh = g_Ghi + (size_t)pl * KCONV;
            __nv_bfloat16* gl = g_Glo + (size_t)pl * KCONV;
            #pragma unroll
            for (int nt = 0; nt < 4; nt++) {
                const int j = nt * 8 + ((lane & 3) << 1);
                const float i0 = s_inv[j], i1 = s_inv[j + 1];
                #pragma unroll
                for (int mt = 0; mt < 2; mt++) {
                    const float* d = acc[mt][nt];
                    const int c0 = w * 32 + mt * 16 + (lane >> 2);
                    uint32_t h, l;
                    split2(d[0] * i0, d[1] * i1, h, l);
                    *((uint32_t*)(gh + c0 * 32 + j)) = h;
                    *((uint32_t*)(gl + c0 * 32 + j)) = l;
                    split2(d[2] * i0, d[3] * i1, h, l);
                    *((uint32_t*)(gh + (c0 + 8) * 32 + j)) = h;
                    *((uint32_t*)(gl + (c0 + 8) * 32 + j)) = l;
                }
            }
        }
        __syncthreads();   // sync3
    }
}

// ---------------------------------------------------------------------------
// bf16 3-term GEMM via mma.sync — 2-stage cp.async double buffer.
// ---------------------------------------------------------------------------
#define OFF_AHI 0
#define OFF_ALO 18432
#define OFF_WHI 36864
#define OFF_WLO 46080
#define STG_SZ  55296
#define GEMM_SMEM (2 * STG_SZ)   // 110592
#define APITCH 72
#define SPITCH 132
#define NKC (KPART / 64)         // 12

__global__ __launch_bounds__(128) void gemm_kernel(int pbase)
{
    extern __shared__ char smem[];
    float*         stg = (float*)smem;
    const uint32_t sb  = smem_u32(smem);

    const int t    = threadIdx.x;
    const int lane = t & 31;
    const int w    = t >> 5;
    const int pl0  = blockIdx.x * 128;
    const int kh   = blockIdx.y;
    const int kb   = kh * KPART;

    float acc[2][8][4];
    #pragma unroll
    for (int mt = 0; mt < 2; mt++)
        #pragma unroll
        for (int nt = 0; nt < 8; nt++)
            #pragma unroll
            for (int i = 0; i < 4; i++) acc[mt][nt][i] = 0.f;

    const int wrow  = t >> 1;
    const int whalf = t & 1;

    const int a_row  = (lane & 15);
    const int a_col  = (lane >> 4) << 3;
    const int b_n    = (lane & 7) + (((lane >> 4) & 1) << 3);
    const int b_koff = ((lane >> 3) & 1) << 3;

    // per-stage tile loader (cp.async, one commit group per call)
    auto issue = [&](int st, int kc) {
        const uint32_t base = sb + st * STG_SZ;
        const char* gh = (const char*)(g_Ghi + (size_t)(pl0 + t) * KCONV + kb + kc * 64);
        const char* gl = (const char*)(g_Glo + (size_t)(pl0 + t) * KCONV + kb + kc * 64);
        #pragma unroll
        for (int j = 0; j < 8; j++) {
            cp16(base + OFF_AHI + (uint32_t)(t * APITCH + j * 8) * 2, gh + j * 16);
            cp16(base + OFF_ALO + (uint32_t)(t * APITCH + j * 8) * 2, gl + j * 16);
        }
        const size_t off = (size_t)wrow * KCONV + kb + kc * 64 + whalf * 32;
        const char* wh = (const char*)(g_Whi + off);
        const char* wl = (const char*)(g_Wlo + off);
        #pragma unroll
        for (int i = 0; i < 4; i++) {
            cp16(base + OFF_WHI + (uint32_t)(wrow * APITCH + whalf * 32 + i * 8) * 2, wh + i * 16);
            cp16(base + OFF_WLO + (uint32_t)(wrow * APITCH + whalf * 32 + i * 8) * 2, wl + i * 16);
        }
        CP_COMMIT();
    };

    issue(0, 0);

    for (int kc = 0; kc < NKC; kc++) {
        if (kc + 1 < NKC) {
            issue((kc + 1) & 1, kc + 1);
            CP_WAIT(1);
        } else {
            CP_WAIT(0);
        }
        __syncthreads();

        const uint32_t stb = sb + (uint32_t)(kc & 1) * STG_SZ;
        #pragma unroll
        for (int s = 0; s < 4; s++) {
            const int k0 = s * 16;
            uint32_t ah[2][4], al[2][4];
            #pragma unroll
            for (int mt = 0; mt < 2; mt++) {
                int row = w * 32 + mt * 16 + a_row;
                ldsm4(ah[mt], stb + OFF_AHI + (uint32_t)(row * APITCH + a_col + k0) * 2);
                ldsm4(al[mt], stb + OFF_ALO + (uint32_t)(row * APITCH + a_col + k0) * 2);
            }
            #pragma unroll
            for (int np = 0; np < 4; np++) {
                int n = np * 16 + b_n;
                uint32_t bh[4], bl[4];
                ldsm4(bh, stb + OFF_WHI + (uint32_t)(n * APITCH + k0 + b_koff) * 2);
                ldsm4(bl, stb + OFF_WLO + (uint32_t)(n * APITCH + k0 + b_koff) * 2);
                #pragma unroll
                for (int mt = 0; mt < 2; mt++) {
                    #pragma unroll
                    for (int hh = 0; hh < 2; hh++) {
                        float* d = acc[mt][np * 2 + hh];
                        mma_bf16(d, ah[mt], bh + hh * 2);
                        mma_bf16(d, ah[mt], bl + hh * 2);
                        mma_bf16(d, al[mt], bh + hh * 2);
                    }
                }
            }
        }
        __syncthreads();   // stage consumed; safe to refill next iteration
    }

    const int lr  = lane >> 2;
    const int lc2 = (lane & 3) << 1;
    #pragma unroll
    for (int mt = 0; mt < 2; mt++) {
        int row0 = w * 32 + mt * 16 + lr;
        #pragma unroll
        for (int nt = 0; nt < 8; nt++) {
            int col = nt * 8 + lc2;
            stg[col * SPITCH + row0]           = acc[mt][nt][0];
            stg[(col + 1) * SPITCH + row0]     = acc[mt][nt][1];
            stg[col * SPITCH + row0 + 8]       = acc[mt][nt][2];
            stg[(col + 1) * SPITCH + row0 + 8] = acc[mt][nt][3];
        }
    }
    __syncthreads();
    for (int i = t; i < 2048; i += 128) {
        int o = i >> 5, q = i & 31;
        float4 v = *((const float4*)(stg + o * SPITCH + q * 4));
        *((float4*)(g_part + ((size_t)kh * COUT + o) * PTOT + pbase + pl0 + q * 4)) = v;
    }
}

// ---------------------------------------------------------------------------
__global__ __launch_bounds__(256) void stats_kernel(
    const float* __restrict__ bconv,
    const float* __restrict__ gamma, const float* __restrict__ beta)
{
    const int o = blockIdx.x;
    const int t = threadIdx.x;
    const float4* r0 = (const float4*)(g_part + ((size_t)0 * COUT + o) * PTOT);
    const float4* r1 = (const float4*)(g_part + ((size_t)1 * COUT + o) * PTOT);
    const float4* r2 = (const float4*)(g_part + ((size_t)2 * COUT + o) * PTOT);
    const float4* r3 = (const float4*)(g_part + ((size_t)3 * COUT + o) * PTOT);
    float4*       pr = (float4*)(g_pre + (size_t)o * PTOT);
    const float bb = bconv[o];

    float s = 0.f, s2 = 0.f;
    for (int i = t; i < PTOT / 4; i += 256) {
        float4 a = r0[i], b = r1[i], c = r2[i], d = r3[i];
        float4 v;
        v.x = a.x + b.x + c.x + d.x + bb;
        v.y = a.y + b.y + c.y + d.y + bb;
        v.z = a.z + b.z + c.z + d.z + bb;
        v.w = a.w + b.w + c.w + d.w + bb;
        pr[i] = v;
        s  += v.x + v.y + v.z + v.w;
        s2 += v.x * v.x + v.y * v.y + v.z * v.z + v.w * v.w;
    }
    __shared__ float rs[256], rs2[256];
    rs[t] = s; rs2[t] = s2;
    __syncthreads();
    for (int st = 128; st > 0; st >>= 1) {
        if (t < st) { rs[t] += rs[t + st]; rs2[t] += rs2[t + st]; }
        __syncthreads();
    }
    if (t == 0) {
        float mean = rs[0] * (1.0f / PTOT);
        float var  = rs2[0] * (1.0f / PTOT) - mean * mean;
        float inv  = rsqrtf(var + 1e-5f);
        float sc   = gamma[o] * inv;
        g_scale[o] = sc;
        g_shift[o] = beta[o] - mean * sc;
    }
}

// ---------------------------------------------------------------------------
__global__ __launch_bounds__(256) void norm_kernel(float* __restrict__ out)
{
    int e = blockIdx.x * 256 + threadIdx.x;
    if (e >= BS * COUT * NPTS / 4) return;
    int nq = e & (NPTS / 4 - 1);
    int o  = (e >> 11) & 63;
    int b  = e >> 17;
    float4 v = *((const float4*)(g_pre + (size_t)o * PTOT + (b << 13)) + nq);
    float sc = g_scale[o], sh = g_shift[o];
    float4 r = make_float4(v.x * sc + sh, v.y * sc + sh, v.z * sc + sh, v.w * sc + sh);
    *((float4*)out + e) = r;
}

// ---------------------------------------------------------------------------
extern "C" void kernel_launch(void* const* d_in, const int* in_sizes, int n_in,
                              void* d_out, int out_size)
{
    const float* x     = (const float*)d_in[0];
    const float* feat  = (const float*)d_in[1];
    const int*   neigh = (const int*)  d_in[2];
    const float* Bmat  = (const float*)d_in[3];
    const float* kern  = (const float*)d_in[4];
    const float* onep  = (const float*)d_in[5];
    const float* Wmlp  = (const float*)d_in[6];
    const float* bmlp  = (const float*)d_in[7];
    const float* Wconv = (const float*)d_in[8];
    const float* bconv = (const float*)d_in[9];
    const float* gamma = (const float*)d_in[10];
    const float* beta  = (const float*)d_in[11];
    float* out = (float*)d_out;

    cudaFuncSetAttribute(gemm_kernel, cudaFuncAttributeMaxDynamicSharedMemorySize, GEMM_SMEM);

    prep_w<<<(COUT * KCONV + 255) / 256, 256>>>(Wconv);
    transpose_f<<<(BS * CIN * NPTS + 255) / 256, 256>>>(feat);
    transpose_x<<<(BS * 3 * NPTS + 255) / 256, 256>>>(x);
    for (int c = 0; c < NCHUNK; c++) {
        point_kernel<<<CHUNK / PPB, 128>>>(c * CHUNK, neigh + (size_t)c * CHUNK * KNB,
                                           Bmat, kern, onep, Wmlp, bmlp);
        gemm_kernel<<<dim3(CHUNK / 128, KSPLIT), 128, GEMM_SMEM>>>(c * CHUNK);
    }
    stats_kernel<<<COUT, 256>>>(bconv, gamma, beta);
    norm_kernel<<<(BS * COUT * NPTS / 4 + 255) / 256, 256>>>(out);
}